// round 1
// baseline (speedup 1.0000x reference)
#include <cuda_runtime.h>
#include <cuda_bf16.h>
#include <math.h>

// Problem constants
#define Bb   2
#define Nn   2048
#define DIM  1024
#define Hh   16
#define DHd  64
#define Mrows (Bb * Nn)          // 4096
#define BHh  (Bb * Hh)           // 32

// Scratch (device globals: allowed; runtime alloc is not)
__device__ float g_Q[BHh * Nn * DHd];   // (b,h,n,dh)
__device__ float g_K[BHh * Nn * DHd];
__device__ float g_V[BHh * Nn * DHd];
__device__ float g_AO[Mrows * DIM];     // attention output, (b,n, h*64+dh)

// ---------------------------------------------------------------------------
// SGEMM "NT": C[m,e] = sum_k A[m,k] * Bw[e,k]  (A: MxK row-major, Bw: NxK row-major)
// MODE 0: C[m*Nn + e] = acc + bias[e]
// MODE 1: write to (b,h,n,dh) layout: C[((b*H + h)*N + n)*DH + dh], b=m/2048, n=m%2048,
//         h=e/64, dh=e%64. (Nn must be 1024.)
// Tiles: 128x128x8, 256 threads, 8x8 per thread. M,N multiples of 128; K multiple of 8.
// ---------------------------------------------------------------------------
template <int MODE>
__global__ __launch_bounds__(256)
void sgemm_nt(const float* __restrict__ A, const float* __restrict__ Bw,
              const float* __restrict__ bias, float* __restrict__ C,
              int M, int Ncols, int K)
{
    __shared__ float As[8][128];
    __shared__ float Bs[8][128];

    const int bm = blockIdx.y * 128;
    const int bn = blockIdx.x * 128;
    const int tid = threadIdx.x;
    const int tx = tid & 15;       // 0..15
    const int ty = tid >> 4;       // 0..15

    const int lr = tid >> 1;           // 0..127 (tile row for loads)
    const int lk = (tid & 1) * 4;      // 0 or 4

    const float* Aptr = A  + (size_t)(bm + lr) * K + lk;
    const float* Bptr = Bw + (size_t)(bn + lr) * K + lk;

    float acc[8][8];
#pragma unroll
    for (int i = 0; i < 8; i++)
#pragma unroll
        for (int j = 0; j < 8; j++) acc[i][j] = 0.0f;

    for (int k0 = 0; k0 < K; k0 += 8) {
        float4 a4 = *(const float4*)(Aptr + k0);
        float4 b4 = *(const float4*)(Bptr + k0);
        As[lk + 0][lr] = a4.x; As[lk + 1][lr] = a4.y;
        As[lk + 2][lr] = a4.z; As[lk + 3][lr] = a4.w;
        Bs[lk + 0][lr] = b4.x; Bs[lk + 1][lr] = b4.y;
        Bs[lk + 2][lr] = b4.z; Bs[lk + 3][lr] = b4.w;
        __syncthreads();

#pragma unroll
        for (int kk = 0; kk < 8; kk++) {
            float a[8], b[8];
            *(float4*)&a[0] = *(const float4*)&As[kk][ty * 8];
            *(float4*)&a[4] = *(const float4*)&As[kk][ty * 8 + 4];
            *(float4*)&b[0] = *(const float4*)&Bs[kk][tx * 8];
            *(float4*)&b[4] = *(const float4*)&Bs[kk][tx * 8 + 4];
#pragma unroll
            for (int i = 0; i < 8; i++)
#pragma unroll
                for (int j = 0; j < 8; j++)
                    acc[i][j] = fmaf(a[i], b[j], acc[i][j]);
        }
        __syncthreads();
    }

    if (MODE == 0) {
#pragma unroll
        for (int i = 0; i < 8; i++) {
            int m = bm + ty * 8 + i;
#pragma unroll
            for (int j = 0; j < 8; j++) {
                int e = bn + tx * 8 + j;
                C[(size_t)m * Ncols + e] = acc[i][j] + bias[e];
            }
        }
    } else {
#pragma unroll
        for (int i = 0; i < 8; i++) {
            int m = bm + ty * 8 + i;
            int b = m >> 11;           // /2048
            int n = m & 2047;
#pragma unroll
            for (int j = 0; j < 8; j++) {
                int e  = bn + tx * 8 + j;
                int h  = e >> 6;
                int dh = e & 63;
                C[(size_t)(((b * Hh + h) * Nn) + n) * DHd + dh] = acc[i][j];
            }
        }
    }
}

// ---------------------------------------------------------------------------
// Per-row L2 normalize over dh=64, multiply by learned scale (H,1,DH) and mult.
// One warp per row; t laid out (b,h,n,dh) contiguous rows of 64.
// ---------------------------------------------------------------------------
__global__ __launch_bounds__(256)
void qk_norm_kernel(float* __restrict__ t, const float* __restrict__ scale, float mult)
{
    int warp = (blockIdx.x * blockDim.x + threadIdx.x) >> 5;
    int lane = threadIdx.x & 31;
    const int nrows = BHh * Nn;
    if (warp >= nrows) return;

    float2* row = (float2*)(t + (size_t)warp * DHd);
    float2 v = row[lane];
    float ss = v.x * v.x + v.y * v.y;
#pragma unroll
    for (int m = 16; m; m >>= 1) ss += __shfl_xor_sync(0xffffffffu, ss, m);

    int h = (warp / Nn) % Hh;
    float inv = mult / fmaxf(sqrtf(ss), 1e-12f);
    const float2* sc = (const float2*)(scale + h * DHd);
    float2 s2 = sc[lane];
    v.x *= inv * s2.x;
    v.y *= inv * s2.y;
    row[lane] = v;
}

// ---------------------------------------------------------------------------
// Flash attention fp32. Q,K,V: (BH, N, 64). Out: (b, n, h*64+dh).
// Block = 64 queries of one (b,h). 256 threads as 16x16, 4x4 register tiles.
// Smem (dynamic): Qst, Kst d-major [64][68]; Vs k-major [64][68]; Pst k-major [64][68].
// ---------------------------------------------------------------------------
#define FS 68   // padded stride (floats), keeps float4 alignment, staggers banks

__global__ __launch_bounds__(256)
void flash_kernel(const float* __restrict__ Q, const float* __restrict__ K,
                  const float* __restrict__ V, float* __restrict__ Out)
{
    extern __shared__ float smem[];
    float* Qst = smem;                 // [d][q]  64*FS
    float* Kst = Qst + 64 * FS;        // [d][k]
    float* Vs  = Kst + 64 * FS;        // [k][d]
    float* Pst = Vs  + 64 * FS;        // [k][q]

    const int tid = threadIdx.x;
    const int tx = tid & 15;
    const int ty = tid >> 4;
    const int bh = blockIdx.y;         // 0..31
    const int q0 = blockIdx.x * 64;
    const int b  = bh >> 4;
    const int h  = bh & 15;

    const float* Qg = Q + ((size_t)bh * Nn + q0) * DHd;

    // Load Q tile transposed (d-major)
#pragma unroll
    for (int it = 0; it < 4; it++) {
        int f4 = it * 256 + tid;           // 0..1023
        int q  = f4 >> 4;
        int dg = (f4 & 15) * 4;
        float4 v4 = *(const float4*)(Qg + (size_t)q * DHd + dg);
        Qst[(dg + 0) * FS + q] = v4.x;
        Qst[(dg + 1) * FS + q] = v4.y;
        Qst[(dg + 2) * FS + q] = v4.z;
        Qst[(dg + 3) * FS + q] = v4.w;
    }

    float Oacc[4][4];
    float mrow[4], lrow[4];
#pragma unroll
    for (int i = 0; i < 4; i++) {
        mrow[i] = -INFINITY; lrow[i] = 0.0f;
#pragma unroll
        for (int j = 0; j < 4; j++) Oacc[i][j] = 0.0f;
    }

    for (int kt = 0; kt < Nn / 64; kt++) {
        if (kt) __syncthreads();   // prev PV done before overwriting K/V

        const float* Kg = K + ((size_t)bh * Nn + kt * 64) * DHd;
        const float* Vg = V + ((size_t)bh * Nn + kt * 64) * DHd;
#pragma unroll
        for (int it = 0; it < 4; it++) {
            int f4 = it * 256 + tid;
            int k  = f4 >> 4;
            int dg = (f4 & 15) * 4;
            float4 kv = *(const float4*)(Kg + (size_t)k * DHd + dg);
            Kst[(dg + 0) * FS + k] = kv.x;
            Kst[(dg + 1) * FS + k] = kv.y;
            Kst[(dg + 2) * FS + k] = kv.z;
            Kst[(dg + 3) * FS + k] = kv.w;
            float4 vv = *(const float4*)(Vg + (size_t)k * DHd + dg);
            *(float4*)&Vs[k * FS + dg] = vv;
        }
        __syncthreads();

        // S = Q K^T  (64q x 64k), this thread: rows ty*4.., cols tx*4..
        float Sv[4][4];
#pragma unroll
        for (int i = 0; i < 4; i++)
#pragma unroll
            for (int j = 0; j < 4; j++) Sv[i][j] = 0.0f;

#pragma unroll 16
        for (int d = 0; d < 64; d++) {
            float4 qa = *(const float4*)&Qst[d * FS + ty * 4];
            float4 kb = *(const float4*)&Kst[d * FS + tx * 4];
            float a[4] = {qa.x, qa.y, qa.z, qa.w};
            float bq[4] = {kb.x, kb.y, kb.z, kb.w};
#pragma unroll
            for (int i = 0; i < 4; i++)
#pragma unroll
                for (int j = 0; j < 4; j++)
                    Sv[i][j] = fmaf(a[i], bq[j], Sv[i][j]);
        }

        // Online softmax (row reduce across tx = 16 lanes)
#pragma unroll
        for (int i = 0; i < 4; i++) {
            float mx = fmaxf(fmaxf(Sv[i][0], Sv[i][1]), fmaxf(Sv[i][2], Sv[i][3]));
#pragma unroll
            for (int off = 1; off < 16; off <<= 1)
                mx = fmaxf(mx, __shfl_xor_sync(0xffffffffu, mx, off));
            float nm = fmaxf(mrow[i], mx);
            float corr = __expf(mrow[i] - nm);   // exp(-inf)=0 on first tile
            float rs = 0.0f;
#pragma unroll
            for (int j = 0; j < 4; j++) {
                Sv[i][j] = __expf(Sv[i][j] - nm);
                rs += Sv[i][j];
            }
#pragma unroll
            for (int off = 1; off < 16; off <<= 1)
                rs += __shfl_xor_sync(0xffffffffu, rs, off);
            lrow[i] = lrow[i] * corr + rs;
            mrow[i] = nm;
#pragma unroll
            for (int j = 0; j < 4; j++) Oacc[i][j] *= corr;
            // stage P (k-major) for PV gemm
#pragma unroll
            for (int j = 0; j < 4; j++)
                Pst[(tx * 4 + j) * FS + ty * 4 + i] = Sv[i][j];
        }
        __syncthreads();

        // O += P @ V   (rows ty*4.. , dh cols tx*4..)
#pragma unroll 16
        for (int kk = 0; kk < 64; kk++) {
            float4 pa = *(const float4*)&Pst[kk * FS + ty * 4];
            float4 vb = *(const float4*)&Vs[kk * FS + tx * 4];
            float a[4] = {pa.x, pa.y, pa.z, pa.w};
            float bv[4] = {vb.x, vb.y, vb.z, vb.w};
#pragma unroll
            for (int i = 0; i < 4; i++)
#pragma unroll
                for (int j = 0; j < 4; j++)
                    Oacc[i][j] = fmaf(a[i], bv[j], Oacc[i][j]);
        }
    }

    // finalize + write (b, n, h*64+dh)
#pragma unroll
    for (int i = 0; i < 4; i++) {
        float inv = 1.0f / lrow[i];
        int n = q0 + ty * 4 + i;
        float* op = Out + ((size_t)b * Nn + n) * DIM + h * DHd + tx * 4;
#pragma unroll
        for (int j = 0; j < 4; j++) op[j] = Oacc[i][j] * inv;
    }
}

// ---------------------------------------------------------------------------
extern "C" void kernel_launch(void* const* d_in, const int* in_sizes, int n_in,
                              void* d_out, int out_size)
{
    const float* x    = (const float*)d_in[0];
    const float* Wq   = (const float*)d_in[1];
    const float* Wk   = (const float*)d_in[2];
    const float* Wv   = (const float*)d_in[3];
    const float* Wo   = (const float*)d_in[4];
    const float* bo   = (const float*)d_in[5];
    const float* qsc  = (const float*)d_in[6];
    const float* ksc  = (const float*)d_in[7];
    float* out = (float*)d_out;

    void *pQ, *pK, *pV, *pAO;
    cudaGetSymbolAddress(&pQ,  g_Q);
    cudaGetSymbolAddress(&pK,  g_K);
    cudaGetSymbolAddress(&pV,  g_V);
    cudaGetSymbolAddress(&pAO, g_AO);

    dim3 gg(DIM / 128, Mrows / 128);   // (8, 32)
    sgemm_nt<1><<<gg, 256>>>(x, Wq, nullptr, (float*)pQ, Mrows, DIM, DIM);
    sgemm_nt<1><<<gg, 256>>>(x, Wk, nullptr, (float*)pK, Mrows, DIM, DIM);
    sgemm_nt<1><<<gg, 256>>>(x, Wv, nullptr, (float*)pV, Mrows, DIM, DIM);

    int nrows = BHh * Nn;                       // 65536
    int nblk = (nrows * 32 + 255) / 256;        // warps*32 / 256
    qk_norm_kernel<<<nblk, 256>>>((float*)pQ, qsc, 0.125f);  // fold DH^-0.5 into Q
    qk_norm_kernel<<<nblk, 256>>>((float*)pK, ksc, 1.0f);

    size_t smem_bytes = 4 * 64 * FS * sizeof(float);  // 69632
    cudaFuncSetAttribute(flash_kernel, cudaFuncAttributeMaxDynamicSharedMemorySize,
                         (int)smem_bytes);
    flash_kernel<<<dim3(Nn / 64, BHh), 256, smem_bytes>>>(
        (const float*)pQ, (const float*)pK, (const float*)pV, (float*)pAO);

    sgemm_nt<0><<<gg, 256>>>((const float*)pAO, Wo, bo, out, Mrows, DIM, DIM);
}

// round 2
// speedup vs baseline: 4.9281x; 4.9281x over previous
#include <cuda_runtime.h>
#include <cuda_fp16.h>
#include <math.h>
#include <stdint.h>

#define Bb   2
#define Nn   2048
#define DIM  1024
#define Hh   16
#define DHd  64
#define Mrows (Bb * Nn)          // 4096
#define BHh  (Bb * Hh)           // 32

// fp16 scratch (device globals)
__device__ __half g_Qh[BHh * Nn * DHd];
__device__ __half g_Kh[BHh * Nn * DHd];
__device__ __half g_Vh[BHh * Nn * DHd];
__device__ __half g_AOh[Mrows * DIM];

// ---------------------------------------------------------------------------
// helpers
// ---------------------------------------------------------------------------
__device__ __forceinline__ uint32_t cvta_s(const void* p) {
    return (uint32_t)__cvta_generic_to_shared(p);
}
__device__ __forceinline__ void ldsm4(uint32_t* r, uint32_t a) {
    asm volatile("ldmatrix.sync.aligned.m8n8.x4.shared.b16 {%0,%1,%2,%3}, [%4];"
                 : "=r"(r[0]), "=r"(r[1]), "=r"(r[2]), "=r"(r[3]) : "r"(a));
}
__device__ __forceinline__ void ldsm4t(uint32_t* r, uint32_t a) {
    asm volatile("ldmatrix.sync.aligned.m8n8.x4.trans.shared.b16 {%0,%1,%2,%3}, [%4];"
                 : "=r"(r[0]), "=r"(r[1]), "=r"(r[2]), "=r"(r[3]) : "r"(a));
}
__device__ __forceinline__ void mma16816(float* c, const uint32_t* a, const uint32_t* b) {
    asm volatile("mma.sync.aligned.m16n8k16.row.col.f32.f16.f16.f32 "
                 "{%0,%1,%2,%3}, {%4,%5,%6,%7}, {%8,%9}, {%0,%1,%2,%3};"
                 : "+f"(c[0]), "+f"(c[1]), "+f"(c[2]), "+f"(c[3])
                 : "r"(a[0]), "r"(a[1]), "r"(a[2]), "r"(a[3]), "r"(b[0]), "r"(b[1]));
}
__device__ __forceinline__ uint32_t pack_h2(float a, float b) {
    __half2 h = __floats2half2_rn(a, b);
    return *reinterpret_cast<uint32_t*>(&h);
}
// fast 2^t on fma/alu pipes (t <= ~0); avoids MUFU. rel err ~1e-7.
__device__ __forceinline__ float fexp2(float t) {
    t = fmaxf(t, -126.0f);
    float n = rintf(t);
    float g = (t - n) * 0.6931471805599453f;     // |g| <= 0.347
    float p = 1.0f + g * (1.0f + g * (0.5f + g * (0.166666667f +
                      g * (0.0416666667f + g * 0.00833333333f))));
    return __int_as_float(__float_as_int(p) + (((int)n) << 23));
}

// ---------------------------------------------------------------------------
// fp16 tensor-core GEMM: C[m,e] = sum_k A[m,k] * Bw[e,k]
// A: M x 1024 (fp32 if AHALF=0, fp16 if AHALF=1), Bw: 1024 x 1024 fp32 (conv on fly)
// EPI 0: fp32 out row-major + bias.  EPI 1: fp16 out to (b,h,n,dh) layout.
// Block 128x128, BK=32, 256 threads (8 warps, 2x4), warp tile 64x32.
// ---------------------------------------------------------------------------
template <int AHALF, int EPI>
__global__ __launch_bounds__(256)
void hgemm(const void* __restrict__ Ap, const float* __restrict__ Bw,
           const float* __restrict__ bias, void* __restrict__ Cp)
{
    __shared__ __align__(16) __half As[2][128][40];
    __shared__ __align__(16) __half Bs[2][128][40];

    const int tid  = threadIdx.x;
    const int warp = tid >> 5, lane = tid & 31;
    const int bm = blockIdx.y * 128, bn = blockIdx.x * 128;
    const int wm = (warp >> 2) * 64, wn = (warp & 3) * 32;

    float c[4][4][4];
#pragma unroll
    for (int i = 0; i < 4; i++)
#pragma unroll
        for (int j = 0; j < 4; j++)
#pragma unroll
            for (int q = 0; q < 4; q++) c[i][j][q] = 0.0f;

    // prefetch registers
    float4 ra[4];          // A fp32 path: 4 float4 (rows t>>3 + i*32, k4=(t&7)*4)
    int4   rah[2];         // A fp16 path: 2 int4
    float4 rb[4];          // B fp32

    const float*  Af = (const float*)Ap;
    const __half* Ah = (const __half*)Ap;

    // ---- load / store helpers (macros for unroll clarity) ----
#define LOAD_TILE(KT)                                                          \
    do {                                                                       \
        int kb = (KT) * 32;                                                    \
        if (AHALF) {                                                           \
            _Pragma("unroll")                                                  \
            for (int i = 0; i < 2; i++) {                                      \
                int id = i * 256 + tid;                                        \
                int m = id >> 2, c8 = (id & 3) * 8;                            \
                rah[i] = *(const int4*)(Ah + (size_t)(bm + m) * 1024 + kb + c8); \
            }                                                                  \
        } else {                                                               \
            _Pragma("unroll")                                                  \
            for (int i = 0; i < 4; i++) {                                      \
                int id = i * 256 + tid;                                        \
                int m = id >> 3, k4 = (id & 7) * 4;                            \
                ra[i] = *(const float4*)(Af + (size_t)(bm + m) * 1024 + kb + k4); \
            }                                                                  \
        }                                                                      \
        _Pragma("unroll")                                                      \
        for (int i = 0; i < 4; i++) {                                          \
            int id = i * 256 + tid;                                            \
            int m = id >> 3, k4 = (id & 7) * 4;                                \
            rb[i] = *(const float4*)(Bw + (size_t)(bn + m) * 1024 + kb + k4);  \
        }                                                                      \
    } while (0)

#define STORE_TILE(BUF)                                                        \
    do {                                                                       \
        if (AHALF) {                                                           \
            _Pragma("unroll")                                                  \
            for (int i = 0; i < 2; i++) {                                      \
                int id = i * 256 + tid;                                        \
                int m = id >> 2, c8 = (id & 3) * 8;                            \
                *(int4*)&As[BUF][m][c8] = rah[i];                              \
            }                                                                  \
        } else {                                                               \
            _Pragma("unroll")                                                  \
            for (int i = 0; i < 4; i++) {                                      \
                int id = i * 256 + tid;                                        \
                int m = id >> 3, k4 = (id & 7) * 4;                            \
                *(__half2*)&As[BUF][m][k4]     = __floats2half2_rn(ra[i].x, ra[i].y); \
                *(__half2*)&As[BUF][m][k4 + 2] = __floats2half2_rn(ra[i].z, ra[i].w); \
            }                                                                  \
        }                                                                      \
        _Pragma("unroll")                                                      \
        for (int i = 0; i < 4; i++) {                                          \
            int id = i * 256 + tid;                                            \
            int m = id >> 3, k4 = (id & 7) * 4;                                \
            *(__half2*)&Bs[BUF][m][k4]     = __floats2half2_rn(rb[i].x, rb[i].y); \
            *(__half2*)&Bs[BUF][m][k4 + 2] = __floats2half2_rn(rb[i].z, rb[i].w); \
        }                                                                      \
    } while (0)

    LOAD_TILE(0);
    STORE_TILE(0);
    __syncthreads();

    for (int kt = 0; kt < 32; kt++) {
        const int buf = kt & 1;
        if (kt < 31) LOAD_TILE(kt + 1);

        // compute on smem[buf]
        uint32_t b[4][4];
#pragma unroll
        for (int in = 0; in < 4; in++)
            ldsm4(b[in], cvta_s(&Bs[buf][wn + in * 8 + (lane & 7)][(lane >> 3) * 8]));
#pragma unroll
        for (int ks = 0; ks < 2; ks++) {
            uint32_t a[4][4];
#pragma unroll
            for (int im = 0; im < 4; im++)
                ldsm4(a[im], cvta_s(&As[buf][wm + im * 16 + (lane & 15)][ks * 16 + (lane >> 4) * 8]));
#pragma unroll
            for (int im = 0; im < 4; im++)
#pragma unroll
                for (int in = 0; in < 4; in++)
                    mma16816(c[im][in], a[im], &b[in][ks * 2]);
        }

        if (kt < 31) STORE_TILE(buf ^ 1);
        __syncthreads();
    }
#undef LOAD_TILE
#undef STORE_TILE

    // epilogue
    const int r = lane >> 2, cq = (lane & 3) * 2;
#pragma unroll
    for (int im = 0; im < 4; im++) {
#pragma unroll
        for (int half_m = 0; half_m < 2; half_m++) {
            int m = bm + wm + im * 16 + r + half_m * 8;
#pragma unroll
            for (int in = 0; in < 4; in++) {
                int e = bn + wn + in * 8 + cq;
                float v0 = c[im][in][half_m * 2 + 0];
                float v1 = c[im][in][half_m * 2 + 1];
                if (EPI == 0) {
                    float* C = (float*)Cp;
                    float2 o = make_float2(v0 + bias[e], v1 + bias[e + 1]);
                    *(float2*)&C[(size_t)m * 1024 + e] = o;
                } else {
                    __half* C = (__half*)Cp;
                    int h = e >> 6, dh = e & 63;
                    int bb = m >> 11, n = m & 2047;
                    *(__half2*)&C[(size_t)(((bb * Hh + h) * Nn) + n) * DHd + dh] =
                        __floats2half2_rn(v0, v1);
                }
            }
        }
    }
}

// ---------------------------------------------------------------------------
// L2 normalize rows of 64 halves, * scale(h,dh) * mult. One warp per row.
// ---------------------------------------------------------------------------
__global__ __launch_bounds__(256)
void qk_norm_h(__half* __restrict__ t, const float* __restrict__ scale, float mult)
{
    int warpid = blockIdx.x * 8 + (threadIdx.x >> 5);
    int lane = threadIdx.x & 31;

    __half2* row = (__half2*)(t + (size_t)warpid * DHd);
    float2 f = __half22float2(row[lane]);
    float ss = f.x * f.x + f.y * f.y;
#pragma unroll
    for (int m = 16; m; m >>= 1) ss += __shfl_xor_sync(0xffffffffu, ss, m);

    int h = (warpid >> 11) & 15;
    float inv = mult / fmaxf(sqrtf(ss), 1e-12f);
    const float2* sc = (const float2*)(scale + h * DHd);
    float2 s2 = sc[lane];
    row[lane] = __floats2half2_rn(f.x * inv * s2.x, f.y * inv * s2.y);
}

// ---------------------------------------------------------------------------
// Flash attention, fp16 MMA + fp32 accum. Q pre-scaled by 0.125*log2e (exp2 softmax).
// CTA: 128 queries of one (b,h); 8 warps, each warp owns 16 query rows.
// Iterate keys in 64-chunks. Out: fp16 (b, n, h*64+dh).
// ---------------------------------------------------------------------------
__global__ __launch_bounds__(256)
void flash_h(const __half* __restrict__ Q, const __half* __restrict__ K,
             const __half* __restrict__ V, __half* __restrict__ Out)
{
    __shared__ __align__(16) __half Qs[128][72];
    __shared__ __align__(16) __half Ks[64][72];
    __shared__ __align__(16) __half Vs[64][72];

    const int tid = threadIdx.x;
    const int warp = tid >> 5, lane = tid & 31;
    const int bh = blockIdx.y;
    const int q0 = blockIdx.x * 128;
    const int b = bh >> 4, h = bh & 15;
    const int r = lane >> 2, cq = (lane & 3) * 2;

    const __half* Qg = Q + ((size_t)bh * Nn + q0) * DHd;
#pragma unroll
    for (int it = 0; it < 4; it++) {
        int id = it * 256 + tid;
        int m = id >> 3, cc = (id & 7) * 8;
        *(int4*)&Qs[m][cc] = *(const int4*)(Qg + m * DHd + cc);
    }

    float O[8][4];
#pragma unroll
    for (int i = 0; i < 8; i++)
#pragma unroll
        for (int j = 0; j < 4; j++) O[i][j] = 0.0f;
    float m0 = -INFINITY, m1 = -INFINITY, l0 = 0.0f, l1 = 0.0f;

    for (int kt = 0; kt < Nn / 64; kt++) {
        __syncthreads();   // previous PV done before K/V overwrite (also orders Q load)
        const __half* Kg = K + ((size_t)bh * Nn + kt * 64) * DHd;
        const __half* Vg = V + ((size_t)bh * Nn + kt * 64) * DHd;
#pragma unroll
        for (int it = 0; it < 2; it++) {
            int id = it * 256 + tid;
            int m = id >> 3, cc = (id & 7) * 8;
            *(int4*)&Ks[m][cc] = *(const int4*)(Kg + m * DHd + cc);
            *(int4*)&Vs[m][cc] = *(const int4*)(Vg + m * DHd + cc);
        }
        __syncthreads();

        // ---- S = Q K^T  (16 rows x 64 keys per warp), base-2 logits ----
        float S[8][4];
#pragma unroll
        for (int i = 0; i < 8; i++)
#pragma unroll
            for (int j = 0; j < 4; j++) S[i][j] = 0.0f;

#pragma unroll
        for (int kh = 0; kh < 2; kh++) {
#pragma unroll
            for (int nh = 0; nh < 2; nh++) {
                uint32_t bk[4][4];
#pragma unroll
                for (int i4 = 0; i4 < 4; i4++) {
                    int in = nh * 4 + i4;
                    ldsm4(bk[i4], cvta_s(&Ks[in * 8 + (lane & 7)][kh * 32 + (lane >> 3) * 8]));
                }
#pragma unroll
                for (int ks2 = 0; ks2 < 2; ks2++) {
                    uint32_t a[4];
                    ldsm4(a, cvta_s(&Qs[warp * 16 + (lane & 15)][(kh * 2 + ks2) * 16 + (lane >> 4) * 8]));
#pragma unroll
                    for (int i4 = 0; i4 < 4; i4++)
                        mma16816(S[nh * 4 + i4], a, &bk[i4][ks2 * 2]);
                }
            }
        }

        // ---- online softmax (exp2 domain) ----
        float mx0 = -INFINITY, mx1 = -INFINITY;
#pragma unroll
        for (int in = 0; in < 8; in++) {
            mx0 = fmaxf(mx0, fmaxf(S[in][0], S[in][1]));
            mx1 = fmaxf(mx1, fmaxf(S[in][2], S[in][3]));
        }
        mx0 = fmaxf(mx0, __shfl_xor_sync(0xffffffffu, mx0, 1));
        mx0 = fmaxf(mx0, __shfl_xor_sync(0xffffffffu, mx0, 2));
        mx1 = fmaxf(mx1, __shfl_xor_sync(0xffffffffu, mx1, 1));
        mx1 = fmaxf(mx1, __shfl_xor_sync(0xffffffffu, mx1, 2));

        float nm0 = fmaxf(m0, mx0), nm1 = fmaxf(m1, mx1);
        float cor0 = fexp2(m0 - nm0), cor1 = fexp2(m1 - nm1);
        float sum0 = 0.0f, sum1 = 0.0f;
#pragma unroll
        for (int in = 0; in < 8; in++) {
            S[in][0] = fexp2(S[in][0] - nm0);
            S[in][1] = fexp2(S[in][1] - nm0);
            S[in][2] = fexp2(S[in][2] - nm1);
            S[in][3] = fexp2(S[in][3] - nm1);
            sum0 += S[in][0] + S[in][1];
            sum1 += S[in][2] + S[in][3];
        }
        sum0 += __shfl_xor_sync(0xffffffffu, sum0, 1);
        sum0 += __shfl_xor_sync(0xffffffffu, sum0, 2);
        sum1 += __shfl_xor_sync(0xffffffffu, sum1, 1);
        sum1 += __shfl_xor_sync(0xffffffffu, sum1, 2);
        l0 = l0 * cor0 + sum0;  m0 = nm0;
        l1 = l1 * cor1 + sum1;  m1 = nm1;
#pragma unroll
        for (int in = 0; in < 8; in++) {
            O[in][0] *= cor0; O[in][1] *= cor0;
            O[in][2] *= cor1; O[in][3] *= cor1;
        }

        // ---- O += P @ V  (P in registers: C-frag -> A-frag) ----
#pragma unroll
        for (int kj = 0; kj < 4; kj++) {
            uint32_t pa[4];
            pa[0] = pack_h2(S[2 * kj][0],     S[2 * kj][1]);
            pa[1] = pack_h2(S[2 * kj][2],     S[2 * kj][3]);
            pa[2] = pack_h2(S[2 * kj + 1][0], S[2 * kj + 1][1]);
            pa[3] = pack_h2(S[2 * kj + 1][2], S[2 * kj + 1][3]);
#pragma unroll
            for (int nv = 0; nv < 4; nv++) {
                uint32_t bv[4];
                ldsm4t(bv, cvta_s(&Vs[kj * 16 + ((lane >> 3) & 1) * 8 + (lane & 7)]
                                    [nv * 16 + (lane >> 4) * 8]));
                mma16816(O[nv * 2],     pa, &bv[0]);
                mma16816(O[nv * 2 + 1], pa, &bv[2]);
            }
        }
    }

    // ---- finalize + store fp16 (b, n, h*64+dh) ----
    float inv0 = 1.0f / l0, inv1 = 1.0f / l1;
    int nrow0 = q0 + warp * 16 + r;
    size_t base0 = ((size_t)b * Nn + nrow0) * DIM + h * DHd;
    size_t base1 = ((size_t)b * Nn + nrow0 + 8) * DIM + h * DHd;
#pragma unroll
    for (int nv = 0; nv < 8; nv++) {
        int col = nv * 8 + cq;
        *(__half2*)(Out + base0 + col) = __floats2half2_rn(O[nv][0] * inv0, O[nv][1] * inv0);
        *(__half2*)(Out + base1 + col) = __floats2half2_rn(O[nv][2] * inv1, O[nv][3] * inv1);
    }
}

// ---------------------------------------------------------------------------
extern "C" void kernel_launch(void* const* d_in, const int* in_sizes, int n_in,
                              void* d_out, int out_size)
{
    const float* x   = (const float*)d_in[0];
    const float* Wq  = (const float*)d_in[1];
    const float* Wk  = (const float*)d_in[2];
    const float* Wv  = (const float*)d_in[3];
    const float* Wo  = (const float*)d_in[4];
    const float* bo  = (const float*)d_in[5];
    const float* qsc = (const float*)d_in[6];
    const float* ksc = (const float*)d_in[7];
    float* out = (float*)d_out;

    void *pQ, *pK, *pV, *pAO;
    cudaGetSymbolAddress(&pQ,  g_Qh);
    cudaGetSymbolAddress(&pK,  g_Kh);
    cudaGetSymbolAddress(&pV,  g_Vh);
    cudaGetSymbolAddress(&pAO, g_AOh);

    dim3 gg(DIM / 128, Mrows / 128);   // (8, 32)
    hgemm<0, 1><<<gg, 256>>>(x, Wq, nullptr, pQ);
    hgemm<0, 1><<<gg, 256>>>(x, Wk, nullptr, pK);
    hgemm<0, 1><<<gg, 256>>>(x, Wv, nullptr, pV);

    // fold 1/sqrt(64) * log2(e) into Q so softmax runs in exp2 domain
    qk_norm_h<<<BHh * Nn / 8, 256>>>((__half*)pQ, qsc, 0.125f * 1.4426950408889634f);
    qk_norm_h<<<BHh * Nn / 8, 256>>>((__half*)pK, ksc, 1.0f);

    flash_h<<<dim3(Nn / 128, BHh), 256>>>((const __half*)pQ, (const __half*)pK,
                                          (const __half*)pV, (__half*)pAO);

    hgemm<1, 0><<<gg, 256>>>(pAO, Wo, bo, out);
}

// round 3
// speedup vs baseline: 6.1272x; 1.2433x over previous
#include <cuda_runtime.h>
#include <cuda_fp16.h>
#include <math.h>
#include <stdint.h>

#define Bb   2
#define Nn   2048
#define DIM  1024
#define Hh   16
#define DHd  64
#define Mrows (Bb * Nn)          // 4096
#define BHh  (Bb * Hh)           // 32

// fp16 scratch (device globals)
__device__ __half g_Xh[Mrows * DIM];            // x in fp16
__device__ __half g_Wqkvh[3 * DIM * DIM];       // [Wq; Wk; Wv] rows
__device__ __half g_Woh[DIM * DIM];
__device__ __half g_Qh[BHh * Nn * DHd];
__device__ __half g_Kh[BHh * Nn * DHd];
__device__ __half g_Vh[BHh * Nn * DHd];
__device__ __half g_AOh[Mrows * DIM];

// ---------------------------------------------------------------------------
// helpers
// ---------------------------------------------------------------------------
__device__ __forceinline__ uint32_t cvta_s(const void* p) {
    return (uint32_t)__cvta_generic_to_shared(p);
}
__device__ __forceinline__ void ldsm4(uint32_t* r, uint32_t a) {
    asm volatile("ldmatrix.sync.aligned.m8n8.x4.shared.b16 {%0,%1,%2,%3}, [%4];"
                 : "=r"(r[0]), "=r"(r[1]), "=r"(r[2]), "=r"(r[3]) : "r"(a));
}
__device__ __forceinline__ void ldsm4t(uint32_t* r, uint32_t a) {
    asm volatile("ldmatrix.sync.aligned.m8n8.x4.trans.shared.b16 {%0,%1,%2,%3}, [%4];"
                 : "=r"(r[0]), "=r"(r[1]), "=r"(r[2]), "=r"(r[3]) : "r"(a));
}
__device__ __forceinline__ void mma16816(float* c, const uint32_t* a, const uint32_t* b) {
    asm volatile("mma.sync.aligned.m16n8k16.row.col.f32.f16.f16.f32 "
                 "{%0,%1,%2,%3}, {%4,%5,%6,%7}, {%8,%9}, {%0,%1,%2,%3};"
                 : "+f"(c[0]), "+f"(c[1]), "+f"(c[2]), "+f"(c[3])
                 : "r"(a[0]), "r"(a[1]), "r"(a[2]), "r"(a[3]), "r"(b[0]), "r"(b[1]));
}
__device__ __forceinline__ uint32_t pack_h2(float a, float b) {
    __half2 h = __floats2half2_rn(a, b);
    return *reinterpret_cast<uint32_t*>(&h);
}
// fast 2^t on fma/alu pipes (t <= ~0); avoids MUFU.
__device__ __forceinline__ float fexp2(float t) {
    t = fmaxf(t, -126.0f);
    float n = rintf(t);
    float g = (t - n) * 0.6931471805599453f;
    float p = 1.0f + g * (1.0f + g * (0.5f + g * (0.166666667f +
                      g * (0.0416666667f + g * 0.00833333333f))));
    return __int_as_float(__float_as_int(p) + (((int)n) << 23));
}

#define CP16(dst, src) asm volatile("cp.async.cg.shared.global [%0], [%1], 16;" \
                                    :: "r"(dst), "l"(src))
#define CPCOMMIT() asm volatile("cp.async.commit_group;")
#define CPWAIT(N)  asm volatile("cp.async.wait_group %0;" :: "n"(N))

// ---------------------------------------------------------------------------
// fp32 -> fp16 convert, 8 elems/thread
// ---------------------------------------------------------------------------
__global__ __launch_bounds__(256)
void f2h(const float* __restrict__ in, __half* __restrict__ out, int n8)
{
    int i = blockIdx.x * 256 + threadIdx.x;
    if (i >= n8) return;
    float4 a = ((const float4*)in)[2 * i];
    float4 b = ((const float4*)in)[2 * i + 1];
    __half2 h[4] = { __floats2half2_rn(a.x, a.y), __floats2half2_rn(a.z, a.w),
                     __floats2half2_rn(b.x, b.y), __floats2half2_rn(b.z, b.w) };
    ((int4*)out)[i] = *reinterpret_cast<int4*>(h);
}

// ---------------------------------------------------------------------------
// fp16 NT GEMM, cp.async 3-stage, 128x128 tile, BK=32, 256 thr (8 warps 2x4).
// C[m,e] = sum_k A[m,k]*B[e,k].
// EPI 0: fp32 out row-major (ldC=1024) + bias.
// EPI 1: QKV demux: which=bn>>10; write fp16 (b,h,n,dh).
// ---------------------------------------------------------------------------
template <int EPI>
__global__ __launch_bounds__(256)
void hgemm(const __half* __restrict__ A, const __half* __restrict__ B,
           const float* __restrict__ bias, float* __restrict__ Cf,
           __half* __restrict__ Qo, __half* __restrict__ Ko, __half* __restrict__ Vo)
{
    extern __shared__ __half sm[];
    __half* As = sm;                    // [3][128][40]
    __half* Bs = sm + 3 * 128 * 40;

    const int tid  = threadIdx.x;
    const int warp = tid >> 5, lane = tid & 31;
    const int bm = blockIdx.y * 128, bn = blockIdx.x * 128;
    const int wm = (warp >> 2) * 64, wn = (warp & 3) * 32;

    const int cm = tid >> 2;            // 0..63? no: tid>>2 = 0..63 — need 0..127
    // copy mapping: 2 iters * 256 threads = 512 chunks per operand
    // id = i*256+tid ; m = id>>2 (0..127), c8 = (id&3)*8

    float c[4][4][4];
#pragma unroll
    for (int i = 0; i < 4; i++)
#pragma unroll
        for (int j = 0; j < 4; j++)
#pragma unroll
            for (int q = 0; q < 4; q++) c[i][j][q] = 0.0f;

#define ISSUE(S, KB)                                                           \
    do {                                                                       \
        _Pragma("unroll")                                                      \
        for (int i = 0; i < 2; i++) {                                          \
            int id = i * 256 + tid;                                            \
            int m = id >> 2, c8 = (id & 3) * 8;                                \
            CP16(cvta_s(As + ((S) * 128 + m) * 40 + c8),                       \
                 A + (size_t)(bm + m) * 1024 + (KB) + c8);                     \
            CP16(cvta_s(Bs + ((S) * 128 + m) * 40 + c8),                       \
                 B + (size_t)(bn + m) * 1024 + (KB) + c8);                     \
        }                                                                      \
    } while (0)

    ISSUE(0, 0);  CPCOMMIT();
    ISSUE(1, 32); CPCOMMIT();

    for (int kt = 0; kt < 32; kt++) {
        if (kt + 2 < 32) ISSUE((kt + 2) % 3, (kt + 2) * 32);
        CPCOMMIT();
        CPWAIT(2);
        __syncthreads();

        const int buf = kt % 3;
        uint32_t b[4][4];
#pragma unroll
        for (int in = 0; in < 4; in++)
            ldsm4(b[in], cvta_s(Bs + (buf * 128 + wn + in * 8 + (lane & 7)) * 40
                                   + (lane >> 3) * 8));
#pragma unroll
        for (int ks = 0; ks < 2; ks++) {
            uint32_t a[4][4];
#pragma unroll
            for (int im = 0; im < 4; im++)
                ldsm4(a[im], cvta_s(As + (buf * 128 + wm + im * 16 + (lane & 15)) * 40
                                       + ks * 16 + (lane >> 4) * 8));
#pragma unroll
            for (int im = 0; im < 4; im++)
#pragma unroll
                for (int in = 0; in < 4; in++)
                    mma16816(c[im][in], a[im], &b[in][ks * 2]);
        }
        __syncthreads();
    }
#undef ISSUE

    // epilogue
    const int r = lane >> 2, cq = (lane & 3) * 2;
    const int which = bn >> 10;                   // EPI=1 only
    __half* dst = (which == 0) ? Qo : (which == 1) ? Ko : Vo;
    const int bnl = bn & 1023;
#pragma unroll
    for (int im = 0; im < 4; im++) {
#pragma unroll
        for (int hm = 0; hm < 2; hm++) {
            int m = bm + wm + im * 16 + r + hm * 8;
#pragma unroll
            for (int in = 0; in < 4; in++) {
                float v0 = c[im][in][hm * 2 + 0];
                float v1 = c[im][in][hm * 2 + 1];
                if (EPI == 0) {
                    int e = bn + wn + in * 8 + cq;
                    *(float2*)&Cf[(size_t)m * 1024 + e] =
                        make_float2(v0 + bias[e], v1 + bias[e + 1]);
                } else {
                    int e  = bnl + wn + in * 8 + cq;
                    int h = e >> 6, dh = e & 63;
                    int bb = m >> 11, n = m & 2047;
                    *(__half2*)&dst[(size_t)(((bb * Hh + h) * Nn) + n) * DHd + dh] =
                        __floats2half2_rn(v0, v1);
                }
            }
        }
    }
    (void)cm;
}

// ---------------------------------------------------------------------------
// Merged Q+K L2-norm: warps [0,65536) -> Q (mult=0.125*log2e), rest -> K.
// ---------------------------------------------------------------------------
__global__ __launch_bounds__(256)
void qk_norm2(__half* __restrict__ Qp, __half* __restrict__ Kp,
              const float* __restrict__ qsc, const float* __restrict__ ksc)
{
    int w = blockIdx.x * 8 + (threadIdx.x >> 5);
    int lane = threadIdx.x & 31;
    const int half = BHh * Nn;                 // 65536
    bool isK = w >= half;
    int wr = isK ? w - half : w;

    __half* t = isK ? Kp : Qp;
    const float* sc = isK ? ksc : qsc;
    float mult = isK ? 1.0f : 0.18033688011112042f;   // 0.125*log2(e)

    __half2* row = (__half2*)(t + (size_t)wr * DHd);
    float2 f = __half22float2(row[lane]);
    float ss = f.x * f.x + f.y * f.y;
#pragma unroll
    for (int m = 16; m; m >>= 1) ss += __shfl_xor_sync(0xffffffffu, ss, m);

    int h = (wr >> 11) & 15;
    float inv = mult / fmaxf(sqrtf(ss), 1e-12f);
    const float2* s = (const float2*)(sc + h * DHd);
    float2 s2 = s[lane];
    row[lane] = __floats2half2_rn(f.x * inv * s2.x, f.y * inv * s2.y);
}

// ---------------------------------------------------------------------------
// Flash attention, fp16 MMA + fp32 accum, cp.async double-buffered K/V.
// CTA: 128 queries of one (b,h); 8 warps * 16 rows. 64-key tiles.
// ---------------------------------------------------------------------------
__global__ __launch_bounds__(256)
void flash_h(const __half* __restrict__ Q, const __half* __restrict__ K,
             const __half* __restrict__ V, __half* __restrict__ Out)
{
    extern __shared__ __half fsm[];
    __half* Qs = fsm;                        // [128][72]
    __half* Ks = fsm + 128 * 72;             // [2][64][72]
    __half* Vs = Ks + 2 * 64 * 72;           // [2][64][72]

    const int tid = threadIdx.x;
    const int warp = tid >> 5, lane = tid & 31;
    const int bh = blockIdx.y;
    const int q0 = blockIdx.x * 128;
    const int b = bh >> 4, h = bh & 15;
    const int r = lane >> 2, cq = (lane & 3) * 2;

    const __half* Qg = Q + ((size_t)bh * Nn + q0) * DHd;
#pragma unroll
    for (int it = 0; it < 4; it++) {
        int id = it * 256 + tid;
        int m = id >> 3, cc = (id & 7) * 8;
        *(int4*)&Qs[m * 72 + cc] = *(const int4*)(Qg + m * DHd + cc);
    }

    const __half* Kg = K + (size_t)bh * Nn * DHd;
    const __half* Vg = V + (size_t)bh * Nn * DHd;

#define ISSUEKV(S, KT)                                                         \
    do {                                                                       \
        _Pragma("unroll")                                                      \
        for (int i = 0; i < 2; i++) {                                          \
            int id = i * 256 + tid;                                            \
            int m = id >> 3, cc = (id & 7) * 8;                                \
            size_t go = (size_t)((KT) * 64 + m) * DHd + cc;                    \
            CP16(cvta_s(Ks + ((S) * 64 + m) * 72 + cc), Kg + go);              \
            CP16(cvta_s(Vs + ((S) * 64 + m) * 72 + cc), Vg + go);              \
        }                                                                      \
    } while (0)

    float O[8][4];
#pragma unroll
    for (int i = 0; i < 8; i++)
#pragma unroll
        for (int j = 0; j < 4; j++) O[i][j] = 0.0f;
    float m0 = -INFINITY, m1 = -INFINITY, l0 = 0.0f, l1 = 0.0f;

    ISSUEKV(0, 0); CPCOMMIT();

    for (int kt = 0; kt < Nn / 64; kt++) {
        if (kt + 1 < Nn / 64) ISSUEKV((kt + 1) & 1, kt + 1);
        CPCOMMIT();
        CPWAIT(1);
        __syncthreads();
        const int st = kt & 1;

        // ---- S = Q K^T ----
        float S[8][4];
#pragma unroll
        for (int i = 0; i < 8; i++)
#pragma unroll
            for (int j = 0; j < 4; j++) S[i][j] = 0.0f;

#pragma unroll
        for (int kh = 0; kh < 2; kh++) {
#pragma unroll
            for (int nh = 0; nh < 2; nh++) {
                uint32_t bk[4][4];
#pragma unroll
                for (int i4 = 0; i4 < 4; i4++) {
                    int in = nh * 4 + i4;
                    ldsm4(bk[i4], cvta_s(Ks + (st * 64 + in * 8 + (lane & 7)) * 72
                                            + kh * 32 + (lane >> 3) * 8));
                }
#pragma unroll
                for (int ks2 = 0; ks2 < 2; ks2++) {
                    uint32_t a[4];
                    ldsm4(a, cvta_s(Qs + (warp * 16 + (lane & 15)) * 72
                                       + (kh * 2 + ks2) * 16 + (lane >> 4) * 8));
#pragma unroll
                    for (int i4 = 0; i4 < 4; i4++)
                        mma16816(S[nh * 4 + i4], a, &bk[i4][ks2 * 2]);
                }
            }
        }

        // ---- online softmax (exp2 domain) ----
        float mx0 = -INFINITY, mx1 = -INFINITY;
#pragma unroll
        for (int in = 0; in < 8; in++) {
            mx0 = fmaxf(mx0, fmaxf(S[in][0], S[in][1]));
            mx1 = fmaxf(mx1, fmaxf(S[in][2], S[in][3]));
        }
        mx0 = fmaxf(mx0, __shfl_xor_sync(0xffffffffu, mx0, 1));
        mx0 = fmaxf(mx0, __shfl_xor_sync(0xffffffffu, mx0, 2));
        mx1 = fmaxf(mx1, __shfl_xor_sync(0xffffffffu, mx1, 1));
        mx1 = fmaxf(mx1, __shfl_xor_sync(0xffffffffu, mx1, 2));

        float nm0 = fmaxf(m0, mx0), nm1 = fmaxf(m1, mx1);
        float cor0 = fexp2(m0 - nm0), cor1 = fexp2(m1 - nm1);
        float sum0 = 0.0f, sum1 = 0.0f;
#pragma unroll
        for (int in = 0; in < 8; in++) {
            S[in][0] = fexp2(S[in][0] - nm0);
            S[in][1] = fexp2(S[in][1] - nm0);
            S[in][2] = fexp2(S[in][2] - nm1);
            S[in][3] = fexp2(S[in][3] - nm1);
            sum0 += S[in][0] + S[in][1];
            sum1 += S[in][2] + S[in][3];
        }
        sum0 += __shfl_xor_sync(0xffffffffu, sum0, 1);
        sum0 += __shfl_xor_sync(0xffffffffu, sum0, 2);
        sum1 += __shfl_xor_sync(0xffffffffu, sum1, 1);
        sum1 += __shfl_xor_sync(0xffffffffu, sum1, 2);
        l0 = l0 * cor0 + sum0;  m0 = nm0;
        l1 = l1 * cor1 + sum1;  m1 = nm1;
#pragma unroll
        for (int in = 0; in < 8; in++) {
            O[in][0] *= cor0; O[in][1] *= cor0;
            O[in][2] *= cor1; O[in][3] *= cor1;
        }

        // ---- O += P @ V ----
#pragma unroll
        for (int kj = 0; kj < 4; kj++) {
            uint32_t pa[4];
            pa[0] = pack_h2(S[2 * kj][0],     S[2 * kj][1]);
            pa[1] = pack_h2(S[2 * kj][2],     S[2 * kj][3]);
            pa[2] = pack_h2(S[2 * kj + 1][0], S[2 * kj + 1][1]);
            pa[3] = pack_h2(S[2 * kj + 1][2], S[2 * kj + 1][3]);
#pragma unroll
            for (int nv = 0; nv < 4; nv++) {
                uint32_t bv[4];
                ldsm4t(bv, cvta_s(Vs + (st * 64 + kj * 16 + ((lane >> 3) & 1) * 8
                                        + (lane & 7)) * 72 + nv * 16 + (lane >> 4) * 8));
                mma16816(O[nv * 2],     pa, &bv[0]);
                mma16816(O[nv * 2 + 1], pa, &bv[2]);
            }
        }
        __syncthreads();
    }
#undef ISSUEKV

    // ---- finalize + store fp16 (b, n, h*64+dh) ----
    float inv0 = 1.0f / l0, inv1 = 1.0f / l1;
    int nrow0 = q0 + warp * 16 + r;
    size_t base0 = ((size_t)b * Nn + nrow0) * DIM + h * DHd;
    size_t base1 = ((size_t)b * Nn + nrow0 + 8) * DIM + h * DHd;
#pragma unroll
    for (int nv = 0; nv < 8; nv++) {
        int col = nv * 8 + cq;
        *(__half2*)(Out + base0 + col) = __floats2half2_rn(O[nv][0] * inv0, O[nv][1] * inv0);
        *(__half2*)(Out + base1 + col) = __floats2half2_rn(O[nv][2] * inv1, O[nv][3] * inv1);
    }
}

// ---------------------------------------------------------------------------
extern "C" void kernel_launch(void* const* d_in, const int* in_sizes, int n_in,
                              void* d_out, int out_size)
{
    const float* x   = (const float*)d_in[0];
    const float* Wq  = (const float*)d_in[1];
    const float* Wk  = (const float*)d_in[2];
    const float* Wv  = (const float*)d_in[3];
    const float* Wo  = (const float*)d_in[4];
    const float* bo  = (const float*)d_in[5];
    const float* qsc = (const float*)d_in[6];
    const float* ksc = (const float*)d_in[7];
    float* out = (float*)d_out;

    __half *Xh, *Wqkvh, *Woh, *Qh, *Kh, *Vh, *AOh;
    cudaGetSymbolAddress((void**)&Xh,    g_Xh);
    cudaGetSymbolAddress((void**)&Wqkvh, g_Wqkvh);
    cudaGetSymbolAddress((void**)&Woh,   g_Woh);
    cudaGetSymbolAddress((void**)&Qh,    g_Qh);
    cudaGetSymbolAddress((void**)&Kh,    g_Kh);
    cudaGetSymbolAddress((void**)&Vh,    g_Vh);
    cudaGetSymbolAddress((void**)&AOh,   g_AOh);

    const int smem_g = 3 * 128 * 40 * 2 * sizeof(__half);   // 61440
    const int smem_f = (128 * 72 + 4 * 64 * 72) * sizeof(__half);  // 55296
    cudaFuncSetAttribute(hgemm<0>, cudaFuncAttributeMaxDynamicSharedMemorySize, smem_g);
    cudaFuncSetAttribute(hgemm<1>, cudaFuncAttributeMaxDynamicSharedMemorySize, smem_g);
    cudaFuncSetAttribute(flash_h,  cudaFuncAttributeMaxDynamicSharedMemorySize, smem_f);

    // fp32 -> fp16 one-time conversions
    f2h<<<Mrows * DIM / 8 / 256, 256>>>(x,  Xh,            Mrows * DIM / 8);
    f2h<<<DIM * DIM / 8 / 256,  256>>>(Wq, Wqkvh,          DIM * DIM / 8);
    f2h<<<DIM * DIM / 8 / 256,  256>>>(Wk, Wqkvh + DIM*DIM,   DIM * DIM / 8);
    f2h<<<DIM * DIM / 8 / 256,  256>>>(Wv, Wqkvh + 2*DIM*DIM, DIM * DIM / 8);
    f2h<<<DIM * DIM / 8 / 256,  256>>>(Wo, Woh,            DIM * DIM / 8);

    // fused QKV projection (N = 3072)
    hgemm<1><<<dim3(3 * DIM / 128, Mrows / 128), 256, smem_g>>>(
        Xh, Wqkvh, nullptr, nullptr, Qh, Kh, Vh);

    qk_norm2<<<2 * BHh * Nn / 8, 256>>>(Qh, Kh, qsc, ksc);

    flash_h<<<dim3(Nn / 128, BHh), 256, smem_f>>>(Qh, Kh, Vh, AOh);

    hgemm<0><<<dim3(DIM / 128, Mrows / 128), 256, smem_g>>>(
        AOh, Woh, bo, out, nullptr, nullptr, nullptr);
}

// round 5
// speedup vs baseline: 6.1634x; 1.0059x over previous
#include <cuda_runtime.h>
#include <cuda_fp16.h>
#include <math.h>
#include <stdint.h>

#define Bb   2
#define Nn   2048
#define DIM  1024
#define Hh   16
#define DHd  64
#define Mrows (Bb * Nn)          // 4096
#define BHh  (Bb * Hh)           // 32
#define QMULT 0.18033688011112042f   // 0.125 * log2(e)

// fp16 scratch (device globals)
__device__ __half g_Xh[Mrows * DIM];
__device__ __half g_Wqkvh[3 * DIM * DIM];
__device__ __half g_Woh[DIM * DIM];
__device__ __half g_Qh[BHh * Nn * DHd];
__device__ __half g_Kh[BHh * Nn * DHd];
__device__ __half g_Vh[BHh * Nn * DHd];
__device__ __half g_AOh[Mrows * DIM];

// ---------------------------------------------------------------------------
// helpers
// ---------------------------------------------------------------------------
__device__ __forceinline__ uint32_t cvta_s(const void* p) {
    return (uint32_t)__cvta_generic_to_shared(p);
}
__device__ __forceinline__ void ldsm4(uint32_t* r, uint32_t a) {
    asm volatile("ldmatrix.sync.aligned.m8n8.x4.shared.b16 {%0,%1,%2,%3}, [%4];"
                 : "=r"(r[0]), "=r"(r[1]), "=r"(r[2]), "=r"(r[3]) : "r"(a));
}
__device__ __forceinline__ void ldsm4t(uint32_t* r, uint32_t a) {
    asm volatile("ldmatrix.sync.aligned.m8n8.x4.trans.shared.b16 {%0,%1,%2,%3}, [%4];"
                 : "=r"(r[0]), "=r"(r[1]), "=r"(r[2]), "=r"(r[3]) : "r"(a));
}
__device__ __forceinline__ void mma16816(float* c, const uint32_t* a, const uint32_t* b) {
    asm volatile("mma.sync.aligned.m16n8k16.row.col.f32.f16.f16.f32 "
                 "{%0,%1,%2,%3}, {%4,%5,%6,%7}, {%8,%9}, {%0,%1,%2,%3};"
                 : "+f"(c[0]), "+f"(c[1]), "+f"(c[2]), "+f"(c[3])
                 : "r"(a[0]), "r"(a[1]), "r"(a[2]), "r"(a[3]), "r"(b[0]), "r"(b[1]));
}
__device__ __forceinline__ uint32_t pack_h2(float a, float b) {
    __half2 h = __floats2half2_rn(a, b);
    return *reinterpret_cast<uint32_t*>(&h);
}
// MUFU exp2 (single issue slot, rt 8) — logits are already base-2
__device__ __forceinline__ float ex2(float x) {
    float y;
    asm("ex2.approx.ftz.f32 %0, %1;" : "=f"(y) : "f"(x));
    return y;
}

#define CP16(dst, src) asm volatile("cp.async.cg.shared.global [%0], [%1], 16;" \
                                    :: "r"(dst), "l"(src))
#define CPCOMMIT() asm volatile("cp.async.commit_group;")
#define CPWAIT(N)  asm volatile("cp.async.wait_group %0;" :: "n"(N))

// ---------------------------------------------------------------------------
// fp32 -> fp16 convert
// ---------------------------------------------------------------------------
__global__ __launch_bounds__(256)
void f2h(const float* __restrict__ in, __half* __restrict__ out, int n8)
{
    int i = blockIdx.x * 256 + threadIdx.x;
    if (i >= n8) return;
    float4 a = ((const float4*)in)[2 * i];
    float4 b = ((const float4*)in)[2 * i + 1];
    __half2 h[4] = { __floats2half2_rn(a.x, a.y), __floats2half2_rn(a.z, a.w),
                     __floats2half2_rn(b.x, b.y), __floats2half2_rn(b.z, b.w) };
    ((int4*)out)[i] = *reinterpret_cast<int4*>(h);
}

// ---------------------------------------------------------------------------
// fp16 HMMA GEMM: C[m,e] = sum_k A[m,k]*B[e,k], K=1024.
// CTA tile 128(M) x 256(N), BK=32, 3-stage cp.async, 256 thr, 8 warps (2x4),
// warp tile 64x64.
// EPI 0: fp32 out (ld 1024) + bias.
// EPI 1: QKV demux + fused L2 norm (Q,K) -> fp16 (b,h,n,dh). V: no norm.
// smem row pitch 40 halves (80 B).
// ---------------------------------------------------------------------------
#define GSTG 30720           // bytes per stage: A 128*80 + B 256*80

template <int EPI>
__global__ __launch_bounds__(256)
void hgemm2(const __half* __restrict__ A, const __half* __restrict__ B,
            const float* __restrict__ bias, float* __restrict__ Cf,
            __half* __restrict__ Qo, __half* __restrict__ Ko, __half* __restrict__ Vo,
            const float* __restrict__ qsc, const float* __restrict__ ksc)
{
    extern __shared__ __align__(16) char gsm[];
    const uint32_t sb = cvta_s(gsm);

    const int tid = threadIdx.x;
    const int warp = tid >> 5, lane = tid & 31;
    const int bm = blockIdx.y * 128, bn = blockIdx.x * 256;
    const int wm = (warp >> 2) * 64, wn = (warp & 3) * 64;

    float c[4][8][4];
#pragma unroll
    for (int i = 0; i < 4; i++)
#pragma unroll
        for (int j = 0; j < 8; j++)
#pragma unroll
            for (int q = 0; q < 4; q++) c[i][j][q] = 0.0f;

#define GISSUE(S, KB)                                                          \
    do {                                                                       \
        uint32_t As = sb + (S) * GSTG;                                         \
        uint32_t Bs = As + 10240;                                              \
        _Pragma("unroll")                                                      \
        for (int it = 0; it < 2; it++) {                                       \
            int id = it * 256 + tid;                                           \
            int m = id >> 2, c4 = id & 3;                                      \
            CP16(As + m * 80 + c4 * 16,                                        \
                 A + (size_t)(bm + m) * 1024 + (KB) + c4 * 8);                 \
        }                                                                      \
        _Pragma("unroll")                                                      \
        for (int it = 0; it < 4; it++) {                                       \
            int id = it * 256 + tid;                                           \
            int m = id >> 2, c4 = id & 3;                                      \
            CP16(Bs + m * 80 + c4 * 16,                                        \
                 B + (size_t)(bn + m) * 1024 + (KB) + c4 * 8);                 \
        }                                                                      \
    } while (0)

    GISSUE(0, 0);  CPCOMMIT();
    GISSUE(1, 32); CPCOMMIT();

    for (int kt = 0; kt < 32; kt++) {
        if (kt + 2 < 32) GISSUE((kt + 2) % 3, (kt + 2) * 32);
        CPCOMMIT();
        CPWAIT(2);
        __syncthreads();

        const uint32_t As = sb + (kt % 3) * GSTG;
        const uint32_t Bs = As + 10240;

        uint32_t b[8][4];
#pragma unroll
        for (int in = 0; in < 8; in++)
            ldsm4(b[in], Bs + (wn + in * 8 + (lane & 7)) * 80 + (lane >> 3) * 16);
#pragma unroll
        for (int ks = 0; ks < 2; ks++) {
            uint32_t a[4][4];
#pragma unroll
            for (int im = 0; im < 4; im++)
                ldsm4(a[im], As + (wm + im * 16 + (lane & 15)) * 80
                               + ks * 32 + (lane >> 4) * 16);
#pragma unroll
            for (int im = 0; im < 4; im++)
#pragma unroll
                for (int in = 0; in < 8; in++)
                    mma16816(c[im][in], a[im], &b[in][ks * 2]);
        }
        __syncthreads();
    }
#undef GISSUE

    // ---- epilogue ----
    const int r = lane >> 2, cq = (lane & 3) * 2;

    if (EPI == 0) {
        float2 bi[8];
#pragma unroll
        for (int in = 0; in < 8; in++)
            bi[in] = *(const float2*)&bias[bn + wn + in * 8 + cq];
#pragma unroll
        for (int im = 0; im < 4; im++)
#pragma unroll
            for (int hm = 0; hm < 2; hm++) {
                int m = bm + wm + im * 16 + hm * 8 + r;
#pragma unroll
                for (int in = 0; in < 8; in++) {
                    int e = bn + wn + in * 8 + cq;
                    *(float2*)&Cf[(size_t)m * 1024 + e] =
                        make_float2(c[im][in][hm * 2] + bi[in].x,
                                    c[im][in][hm * 2 + 1] + bi[in].y);
                }
            }
    } else {
        const int which = bn >> 10;                  // 0=Q 1=K 2=V
        const int bnl = bn & 1023;
        __half* dst = (which == 0) ? Qo : (which == 1) ? Ko : Vo;
        const int h = (bnl + wn) >> 6;               // warp tile = one head
        const float mult = (which == 0) ? QMULT : 1.0f;
        const float* sc = (which == 0) ? qsc : ksc;

        float2 s2[8];
        if (which < 2) {
#pragma unroll
            for (int in = 0; in < 8; in++)
                s2[in] = *(const float2*)&sc[h * 64 + in * 8 + cq];
        } else {
#pragma unroll
            for (int in = 0; in < 8; in++) s2[in] = make_float2(1.0f, 1.0f);
        }

#pragma unroll
        for (int im = 0; im < 4; im++)
#pragma unroll
            for (int hm = 0; hm < 2; hm++) {
                float inv = 1.0f;
                if (which < 2) {
                    float ss = 0.0f;
#pragma unroll
                    for (int in = 0; in < 8; in++)
                        ss += c[im][in][hm * 2] * c[im][in][hm * 2]
                            + c[im][in][hm * 2 + 1] * c[im][in][hm * 2 + 1];
                    ss += __shfl_xor_sync(0xffffffffu, ss, 1);
                    ss += __shfl_xor_sync(0xffffffffu, ss, 2);
                    inv = mult / fmaxf(sqrtf(ss), 1e-12f);
                }
                int m = bm + wm + im * 16 + hm * 8 + r;
                int bbq = m >> 11, n = m & 2047;
                __half* row = dst + (size_t)(((bbq * Hh + h) * Nn) + n) * DHd;
#pragma unroll
                for (int in = 0; in < 8; in++) {
                    int dh = in * 8 + cq;
                    *(__half2*)&row[dh] = __floats2half2_rn(
                        c[im][in][hm * 2] * inv * s2[in].x,
                        c[im][in][hm * 2 + 1] * inv * s2[in].y);
                }
            }
    }
}

// ---------------------------------------------------------------------------
// Flash attention, fp16 MMA + fp32 accum, cp.async double-buffered K/V,
// Q fragments hoisted, MUFU exp2 softmax.
// CTA: 128 queries of one (b,h); 8 warps * 16 rows; 64-key tiles.
// ---------------------------------------------------------------------------
__global__ __launch_bounds__(256)
void flash_h(const __half* __restrict__ Q, const __half* __restrict__ K,
             const __half* __restrict__ V, __half* __restrict__ Out)
{
    extern __shared__ __half fsm[];
    __half* Qs = fsm;                        // [128][72]
    __half* Ks = fsm + 128 * 72;             // [2][64][72]
    __half* Vs = Ks + 2 * 64 * 72;           // [2][64][72]

    const int tid = threadIdx.x;
    const int warp = tid >> 5, lane = tid & 31;
    const int bh = blockIdx.y;
    const int q0 = blockIdx.x * 128;
    const int b = bh >> 4, h = bh & 15;
    const int r = lane >> 2, cq = (lane & 3) * 2;

    const __half* Qg = Q + ((size_t)bh * Nn + q0) * DHd;
#pragma unroll
    for (int it = 0; it < 4; it++) {
        int id = it * 256 + tid;
        int m = id >> 3, cc = (id & 7) * 8;
        *(int4*)&Qs[m * 72 + cc] = *(const int4*)(Qg + m * DHd + cc);
    }

    const __half* Kg = K + (size_t)bh * Nn * DHd;
    const __half* Vg = V + (size_t)bh * Nn * DHd;

#define ISSUEKV(S, KT)                                                         \
    do {                                                                       \
        _Pragma("unroll")                                                      \
        for (int i = 0; i < 2; i++) {                                          \
            int id = i * 256 + tid;                                            \
            int m = id >> 3, cc = (id & 7) * 8;                                \
            size_t go = (size_t)((KT) * 64 + m) * DHd + cc;                    \
            CP16(cvta_s(Ks + ((S) * 64 + m) * 72 + cc), Kg + go);              \
            CP16(cvta_s(Vs + ((S) * 64 + m) * 72 + cc), Vg + go);              \
        }                                                                      \
    } while (0)

    ISSUEKV(0, 0); CPCOMMIT();
    __syncthreads();                         // Qs visible to all warps

    // hoist Q fragments (loop-invariant)
    uint32_t aq[4][4];
#pragma unroll
    for (int kq = 0; kq < 4; kq++)
        ldsm4(aq[kq], cvta_s(Qs + (warp * 16 + (lane & 15)) * 72
                                + kq * 16 + (lane >> 4) * 8));

    float O[8][4];
#pragma unroll
    for (int i = 0; i < 8; i++)
#pragma unroll
        for (int j = 0; j < 4; j++) O[i][j] = 0.0f;
    float m0 = -INFINITY, m1 = -INFINITY, l0 = 0.0f, l1 = 0.0f;

    for (int kt = 0; kt < Nn / 64; kt++) {
        if (kt + 1 < Nn / 64) ISSUEKV((kt + 1) & 1, kt + 1);
        CPCOMMIT();
        CPWAIT(1);
        __syncthreads();
        const int st = kt & 1;

        float S[8][4];
#pragma unroll
        for (int i = 0; i < 8; i++)
#pragma unroll
            for (int j = 0; j < 4; j++) S[i][j] = 0.0f;

#pragma unroll
        for (int kh = 0; kh < 2; kh++) {
#pragma unroll
            for (int nh = 0; nh < 2; nh++) {
                uint32_t bk[4][4];
#pragma unroll
                for (int i4 = 0; i4 < 4; i4++) {
                    int in = nh * 4 + i4;
                    ldsm4(bk[i4], cvta_s(Ks + (st * 64 + in * 8 + (lane & 7)) * 72
                                            + kh * 32 + (lane >> 3) * 8));
                }
#pragma unroll
                for (int ks2 = 0; ks2 < 2; ks2++) {
#pragma unroll
                    for (int i4 = 0; i4 < 4; i4++)
                        mma16816(S[nh * 4 + i4], aq[kh * 2 + ks2], &bk[i4][ks2 * 2]);
                }
            }
        }

        float mx0 = -INFINITY, mx1 = -INFINITY;
#pragma unroll
        for (int in = 0; in < 8; in++) {
            mx0 = fmaxf(mx0, fmaxf(S[in][0], S[in][1]));
            mx1 = fmaxf(mx1, fmaxf(S[in][2], S[in][3]));
        }
        mx0 = fmaxf(mx0, __shfl_xor_sync(0xffffffffu, mx0, 1));
        mx0 = fmaxf(mx0, __shfl_xor_sync(0xffffffffu, mx0, 2));
        mx1 = fmaxf(mx1, __shfl_xor_sync(0xffffffffu, mx1, 1));
        mx1 = fmaxf(mx1, __shfl_xor_sync(0xffffffffu, mx1, 2));

        float nm0 = fmaxf(m0, mx0), nm1 = fmaxf(m1, mx1);
        float cor0 = ex2(m0 - nm0), cor1 = ex2(m1 - nm1);
        float sum0 = 0.0f, sum1 = 0.0f;
#pragma unroll
        for (int in = 0; in < 8; in++) {
            S[in][0] = ex2(S[in][0] - nm0);
            S[in][1] = ex2(S[in][1] - nm0);
            S[in][2] = ex2(S[in][2] - nm1);
            S[in][3] = ex2(S[in][3] - nm1);
            sum0 += S[in][0] + S[in][1];
            sum1 += S[in][2] + S[in][3];
        }
        sum0 += __shfl_xor_sync(0xffffffffu, sum0, 1);
        sum0 += __shfl_xor_sync(0xffffffffu, sum0, 2);
        sum1 += __shfl_xor_sync(0xffffffffu, sum1, 1);
        sum1 += __shfl_xor_sync(0xffffffffu, sum1, 2);
        l0 = l0 * cor0 + sum0;  m0 = nm0;
        l1 = l1 * cor1 + sum1;  m1 = nm1;
#pragma unroll
        for (int in = 0; in < 8; in++) {
            O[in][0] *= cor0; O[in][1] *= cor0;
            O[in][2] *= cor1; O[in][3] *= cor1;
        }

#pragma unroll
        for (int kj = 0; kj < 4; kj++) {
            uint32_t pa[4];
            pa[0] = pack_h2(S[2 * kj][0],     S[2 * kj][1]);
            pa[1] = pack_h2(S[2 * kj][2],     S[2 * kj][3]);
            pa[2] = pack_h2(S[2 * kj + 1][0], S[2 * kj + 1][1]);
            pa[3] = pack_h2(S[2 * kj + 1][2], S[2 * kj + 1][3]);
#pragma unroll
            for (int nv = 0; nv < 4; nv++) {
                uint32_t bv[4];
                ldsm4t(bv, cvta_s(Vs + (st * 64 + kj * 16 + ((lane >> 3) & 1) * 8
                                        + (lane & 7)) * 72 + nv * 16 + (lane >> 4) * 8));
                mma16816(O[nv * 2],     pa, &bv[0]);
                mma16816(O[nv * 2 + 1], pa, &bv[2]);
            }
        }
        __syncthreads();
    }
#undef ISSUEKV

    float inv0 = 1.0f / l0, inv1 = 1.0f / l1;
    int nrow0 = q0 + warp * 16 + r;
    size_t base0 = ((size_t)b * Nn + nrow0) * DIM + h * DHd;
    size_t base1 = ((size_t)b * Nn + nrow0 + 8) * DIM + h * DHd;
#pragma unroll
    for (int nv = 0; nv < 8; nv++) {
        int col = nv * 8 + cq;
        *(__half2*)(Out + base0 + col) = __floats2half2_rn(O[nv][0] * inv0, O[nv][1] * inv0);
        *(__half2*)(Out + base1 + col) = __floats2half2_rn(O[nv][2] * inv1, O[nv][3] * inv1);
    }
}

// ---------------------------------------------------------------------------
extern "C" void kernel_launch(void* const* d_in, const int* in_sizes, int n_in,
                              void* d_out, int out_size)
{
    const float* x   = (const float*)d_in[0];
    const float* Wq  = (const float*)d_in[1];
    const float* Wk  = (const float*)d_in[2];
    const float* Wv  = (const float*)d_in[3];
    const float* Wo  = (const float*)d_in[4];
    const float* bo  = (const float*)d_in[5];
    const float* qsc = (const float*)d_in[6];
    const float* ksc = (const float*)d_in[7];
    float* out = (float*)d_out;

    __half *Xh, *Wqkvh, *Woh, *Qh, *Kh, *Vh, *AOh;
    cudaGetSymbolAddress((void**)&Xh,    g_Xh);
    cudaGetSymbolAddress((void**)&Wqkvh, g_Wqkvh);
    cudaGetSymbolAddress((void**)&Woh,   g_Woh);
    cudaGetSymbolAddress((void**)&Qh,    g_Qh);
    cudaGetSymbolAddress((void**)&Kh,    g_Kh);
    cudaGetSymbolAddress((void**)&Vh,    g_Vh);
    cudaGetSymbolAddress((void**)&AOh,   g_AOh);

    const int smem_g = 3 * GSTG;                               // 92160
    const int smem_f = (128 * 72 + 4 * 64 * 72) * sizeof(__half);  // 55296
    cudaFuncSetAttribute(hgemm2<0>, cudaFuncAttributeMaxDynamicSharedMemorySize, smem_g);
    cudaFuncSetAttribute(hgemm2<1>, cudaFuncAttributeMaxDynamicSharedMemorySize, smem_g);
    cudaFuncSetAttribute(flash_h,   cudaFuncAttributeMaxDynamicSharedMemorySize, smem_f);

    f2h<<<Mrows * DIM / 8 / 256, 256>>>(x,  Xh,                   Mrows * DIM / 8);
    f2h<<<DIM * DIM / 8 / 256,  256>>>(Wq, Wqkvh,                 DIM * DIM / 8);
    f2h<<<DIM * DIM / 8 / 256,  256>>>(Wk, Wqkvh + DIM * DIM,     DIM * DIM / 8);
    f2h<<<DIM * DIM / 8 / 256,  256>>>(Wv, Wqkvh + 2 * DIM * DIM, DIM * DIM / 8);
    f2h<<<DIM * DIM / 8 / 256,  256>>>(Wo, Woh,                   DIM * DIM / 8);

    // fused QKV projection + QK norm: N = 3072 in 256-wide tiles
    hgemm2<1><<<dim3(3 * DIM / 256, Mrows / 128), 256, smem_g>>>(
        Xh, Wqkvh, nullptr, nullptr, Qh, Kh, Vh, qsc, ksc);

    flash_h<<<dim3(Nn / 128, BHh), 256, smem_f>>>(Qh, Kh, Vh, AOh);

    // output projection
    hgemm2<0><<<dim3(DIM / 256, Mrows / 128), 256, smem_g>>>(
        AOh, Woh, bo, out, nullptr, nullptr, nullptr, nullptr, nullptr);
}

// round 6
// speedup vs baseline: 7.0206x; 1.1391x over previous
#include <cuda_runtime.h>
#include <cuda_fp16.h>
#include <math.h>
#include <stdint.h>

#define Bb   2
#define Nn   2048
#define DIM  1024
#define Hh   16
#define DHd  64
#define Mrows (Bb * Nn)          // 4096
#define BHh  (Bb * Hh)           // 32
#define QMULT 0.18033688011112042f   // 0.125 * log2(e)

// fp16 scratch (device globals)
__device__ __half g_Xh[Mrows * DIM];
__device__ __half g_Wqkvh[3 * DIM * DIM];
__device__ __half g_Woh[DIM * DIM];
__device__ __half g_Qh[BHh * Nn * DHd];
__device__ __half g_Kh[BHh * Nn * DHd];
__device__ __half g_Vh[BHh * Nn * DHd];
__device__ __half g_AOh[Mrows * DIM];

// ---------------------------------------------------------------------------
// helpers
// ---------------------------------------------------------------------------
__device__ __forceinline__ uint32_t cvta_s(const void* p) {
    return (uint32_t)__cvta_generic_to_shared(p);
}
__device__ __forceinline__ void ldsm4(uint32_t* r, uint32_t a) {
    asm volatile("ldmatrix.sync.aligned.m8n8.x4.shared.b16 {%0,%1,%2,%3}, [%4];"
                 : "=r"(r[0]), "=r"(r[1]), "=r"(r[2]), "=r"(r[3]) : "r"(a));
}
__device__ __forceinline__ void ldsm4t(uint32_t* r, uint32_t a) {
    asm volatile("ldmatrix.sync.aligned.m8n8.x4.trans.shared.b16 {%0,%1,%2,%3}, [%4];"
                 : "=r"(r[0]), "=r"(r[1]), "=r"(r[2]), "=r"(r[3]) : "r"(a));
}
__device__ __forceinline__ void mma16816(float* c, const uint32_t* a, const uint32_t* b) {
    asm volatile("mma.sync.aligned.m16n8k16.row.col.f32.f16.f16.f32 "
                 "{%0,%1,%2,%3}, {%4,%5,%6,%7}, {%8,%9}, {%0,%1,%2,%3};"
                 : "+f"(c[0]), "+f"(c[1]), "+f"(c[2]), "+f"(c[3])
                 : "r"(a[0]), "r"(a[1]), "r"(a[2]), "r"(a[3]), "r"(b[0]), "r"(b[1]));
}
__device__ __forceinline__ uint32_t pack_h2(float a, float b) {
    __half2 h = __floats2half2_rn(a, b);
    return *reinterpret_cast<uint32_t*>(&h);
}
__device__ __forceinline__ float ex2(float x) {
    float y;
    asm("ex2.approx.ftz.f32 %0, %1;" : "=f"(y) : "f"(x));
    return y;
}

#define CP16(dst, src) asm volatile("cp.async.cg.shared.global [%0], [%1], 16;" \
                                    :: "r"(dst), "l"(src))
#define CPCOMMIT() asm volatile("cp.async.commit_group;")
#define CPWAIT(N)  asm volatile("cp.async.wait_group %0;" :: "n"(N))

// ---------------------------------------------------------------------------
// merged fp32 -> fp16 conversion: x, Wq, Wk, Wv, Wo in one launch.
// unit = 8 floats. segments: x 524288, then 4 x 131072.
// ---------------------------------------------------------------------------
__global__ __launch_bounds__(256)
void convert_all(const float* __restrict__ x,  const float* __restrict__ Wq,
                 const float* __restrict__ Wk, const float* __restrict__ Wv,
                 const float* __restrict__ Wo,
                 __half* __restrict__ Xh, __half* __restrict__ Wqkvh,
                 __half* __restrict__ Woh)
{
    int i = blockIdx.x * 256 + threadIdx.x;     // 0 .. 1048575
    const float* src;
    __half* dst;
    int j = i;
    if (j < 524288)      { src = x;  dst = Xh; }
    else {
        j -= 524288;
        if (j < 131072)      { src = Wq; dst = Wqkvh; }
        else { j -= 131072;
            if (j < 131072)  { src = Wk; dst = Wqkvh + 1048576; }
            else { j -= 131072;
                if (j < 131072) { src = Wv; dst = Wqkvh + 2097152; }
                else { j -= 131072; src = Wo; dst = Woh; }
            }
        }
    }
    float4 a = ((const float4*)src)[2 * j];
    float4 b = ((const float4*)src)[2 * j + 1];
    __half2 h[4] = { __floats2half2_rn(a.x, a.y), __floats2half2_rn(a.z, a.w),
                     __floats2half2_rn(b.x, b.y), __floats2half2_rn(b.z, b.w) };
    ((int4*)dst)[j] = *reinterpret_cast<int4*>(h);
}

// ---------------------------------------------------------------------------
// fp16 HMMA GEMM: C[m,e] = sum_k A[m,k]*B[e,k], K=1024.
// CTA 128x256, BK=32, 3-stage cp.async, single sync/iter, 8 warps, warp 64x64.
// EPI 0: fp32 out + bias. EPI 1: QKV demux + fused L2 norm.
// ---------------------------------------------------------------------------
#define GSTG 30720           // bytes per stage: A 128*80 + B 256*80

template <int EPI>
__global__ __launch_bounds__(256)
void hgemm2(const __half* __restrict__ A, const __half* __restrict__ B,
            const float* __restrict__ bias, float* __restrict__ Cf,
            __half* __restrict__ Qo, __half* __restrict__ Ko, __half* __restrict__ Vo,
            const float* __restrict__ qsc, const float* __restrict__ ksc)
{
    extern __shared__ __align__(16) char gsm[];
    const uint32_t sb = cvta_s(gsm);

    const int tid = threadIdx.x;
    const int warp = tid >> 5, lane = tid & 31;
    const int bm = blockIdx.y * 128, bn = blockIdx.x * 256;
    const int wm = (warp >> 2) * 64, wn = (warp & 3) * 64;

    float c[4][8][4];
#pragma unroll
    for (int i = 0; i < 4; i++)
#pragma unroll
        for (int j = 0; j < 8; j++)
#pragma unroll
            for (int q = 0; q < 4; q++) c[i][j][q] = 0.0f;

#define GISSUE(S, KB)                                                          \
    do {                                                                       \
        uint32_t As = sb + (S) * GSTG;                                         \
        uint32_t Bs = As + 10240;                                              \
        _Pragma("unroll")                                                      \
        for (int it = 0; it < 2; it++) {                                       \
            int id = it * 256 + tid;                                           \
            int m = id >> 2, c4 = id & 3;                                      \
            CP16(As + m * 80 + c4 * 16,                                        \
                 A + (size_t)(bm + m) * 1024 + (KB) + c4 * 8);                 \
        }                                                                      \
        _Pragma("unroll")                                                      \
        for (int it = 0; it < 4; it++) {                                       \
            int id = it * 256 + tid;                                           \
            int m = id >> 2, c4 = id & 3;                                      \
            CP16(Bs + m * 80 + c4 * 16,                                        \
                 B + (size_t)(bn + m) * 1024 + (KB) + c4 * 8);                 \
        }                                                                      \
    } while (0)

    GISSUE(0, 0);  CPCOMMIT();
    GISSUE(1, 32); CPCOMMIT();

    for (int kt = 0; kt < 32; kt++) {
        // stage kt ready?  (outstanding: kt, kt+1 — except near the tail)
        if (kt >= 30) CPWAIT(0); else CPWAIT(1);
        __syncthreads();     // loads visible + stage (kt+2)%3 free for overwrite

        if (kt + 2 < 32) { GISSUE((kt + 2) % 3, (kt + 2) * 32); CPCOMMIT(); }

        const uint32_t As = sb + (kt % 3) * GSTG;
        const uint32_t Bs = As + 10240;

        uint32_t b[8][4];
#pragma unroll
        for (int in = 0; in < 8; in++)
            ldsm4(b[in], Bs + (wn + in * 8 + (lane & 7)) * 80 + (lane >> 3) * 16);
#pragma unroll
        for (int ks = 0; ks < 2; ks++) {
            uint32_t a[4][4];
#pragma unroll
            for (int im = 0; im < 4; im++)
                ldsm4(a[im], As + (wm + im * 16 + (lane & 15)) * 80
                               + ks * 32 + (lane >> 4) * 16);
#pragma unroll
            for (int im = 0; im < 4; im++)
#pragma unroll
                for (int in = 0; in < 8; in++)
                    mma16816(c[im][in], a[im], &b[in][ks * 2]);
        }
    }
#undef GISSUE

    // ---- epilogue ----
    const int r = lane >> 2, cq = (lane & 3) * 2;

    if (EPI == 0) {
        float2 bi[8];
#pragma unroll
        for (int in = 0; in < 8; in++)
            bi[in] = *(const float2*)&bias[bn + wn + in * 8 + cq];
#pragma unroll
        for (int im = 0; im < 4; im++)
#pragma unroll
            for (int hm = 0; hm < 2; hm++) {
                int m = bm + wm + im * 16 + hm * 8 + r;
#pragma unroll
                for (int in = 0; in < 8; in++) {
                    int e = bn + wn + in * 8 + cq;
                    *(float2*)&Cf[(size_t)m * 1024 + e] =
                        make_float2(c[im][in][hm * 2] + bi[in].x,
                                    c[im][in][hm * 2 + 1] + bi[in].y);
                }
            }
    } else {
        const int which = bn >> 10;                  // 0=Q 1=K 2=V
        const int bnl = bn & 1023;
        __half* dst = (which == 0) ? Qo : (which == 1) ? Ko : Vo;
        const int h = (bnl + wn) >> 6;               // warp tile = one head
        const float mult = (which == 0) ? QMULT : 1.0f;
        const float* sc = (which == 0) ? qsc : ksc;

        float2 s2[8];
        if (which < 2) {
#pragma unroll
            for (int in = 0; in < 8; in++)
                s2[in] = *(const float2*)&sc[h * 64 + in * 8 + cq];
        } else {
#pragma unroll
            for (int in = 0; in < 8; in++) s2[in] = make_float2(1.0f, 1.0f);
        }

#pragma unroll
        for (int im = 0; im < 4; im++)
#pragma unroll
            for (int hm = 0; hm < 2; hm++) {
                float inv = 1.0f;
                if (which < 2) {
                    float ss = 0.0f;
#pragma unroll
                    for (int in = 0; in < 8; in++)
                        ss += c[im][in][hm * 2] * c[im][in][hm * 2]
                            + c[im][in][hm * 2 + 1] * c[im][in][hm * 2 + 1];
                    ss += __shfl_xor_sync(0xffffffffu, ss, 1);
                    ss += __shfl_xor_sync(0xffffffffu, ss, 2);
                    inv = mult / fmaxf(sqrtf(ss), 1e-12f);
                }
                int m = bm + wm + im * 16 + hm * 8 + r;
                int bbq = m >> 11, n = m & 2047;
                __half* row = dst + (size_t)(((bbq * Hh + h) * Nn) + n) * DHd;
#pragma unroll
                for (int in = 0; in < 8; in++) {
                    int dh = in * 8 + cq;
                    *(__half2*)&row[dh] = __floats2half2_rn(
                        c[im][in][hm * 2] * inv * s2[in].x,
                        c[im][in][hm * 2 + 1] * inv * s2[in].y);
                }
            }
    }
}

// ---------------------------------------------------------------------------
// Flash attention, fp16 MMA + fp32 accum, cp.async TRIPLE-buffered K/V,
// single sync/iter, Q fragments hoisted, MUFU exp2.
// CTA: 128 queries of one (b,h); 8 warps * 16 rows; 64-key tiles, 32 tiles.
// smem: Qs[128][72] + Ks[3][64][72] + Vs[3][64][72] = 73728 B.
// ---------------------------------------------------------------------------
__global__ __launch_bounds__(256)
void flash_h(const __half* __restrict__ Q, const __half* __restrict__ K,
             const __half* __restrict__ V, __half* __restrict__ Out)
{
    extern __shared__ __half fsm[];
    __half* Qs = fsm;                        // [128][72]
    __half* Ks = fsm + 128 * 72;             // [3][64][72]
    __half* Vs = Ks + 3 * 64 * 72;           // [3][64][72]

    const int tid = threadIdx.x;
    const int warp = tid >> 5, lane = tid & 31;
    const int bh = blockIdx.y;
    const int q0 = blockIdx.x * 128;
    const int b = bh >> 4, h = bh & 15;
    const int r = lane >> 2, cq = (lane & 3) * 2;

    const __half* Qg = Q + ((size_t)bh * Nn + q0) * DHd;
#pragma unroll
    for (int it = 0; it < 4; it++) {
        int id = it * 256 + tid;
        int m = id >> 3, cc = (id & 7) * 8;
        *(int4*)&Qs[m * 72 + cc] = *(const int4*)(Qg + m * DHd + cc);
    }

    const __half* Kg = K + (size_t)bh * Nn * DHd;
    const __half* Vg = V + (size_t)bh * Nn * DHd;

#define ISSUEKV(S, KT)                                                         \
    do {                                                                       \
        _Pragma("unroll")                                                      \
        for (int i = 0; i < 2; i++) {                                          \
            int id = i * 256 + tid;                                            \
            int m = id >> 3, cc = (id & 7) * 8;                                \
            size_t go = (size_t)((KT) * 64 + m) * DHd + cc;                    \
            CP16(cvta_s(Ks + ((S) * 64 + m) * 72 + cc), Kg + go);              \
            CP16(cvta_s(Vs + ((S) * 64 + m) * 72 + cc), Vg + go);              \
        }                                                                      \
    } while (0)

    ISSUEKV(0, 0); CPCOMMIT();
    ISSUEKV(1, 1); CPCOMMIT();
    __syncthreads();                         // Qs visible to all warps

    // hoist Q fragments (loop-invariant)
    uint32_t aq[4][4];
#pragma unroll
    for (int kq = 0; kq < 4; kq++)
        ldsm4(aq[kq], cvta_s(Qs + (warp * 16 + (lane & 15)) * 72
                                + kq * 16 + (lane >> 4) * 8));

    float O[8][4];
#pragma unroll
    for (int i = 0; i < 8; i++)
#pragma unroll
        for (int j = 0; j < 4; j++) O[i][j] = 0.0f;
    float m0 = -INFINITY, m1 = -INFINITY, l0 = 0.0f, l1 = 0.0f;

    for (int kt = 0; kt < 32; kt++) {
        if (kt >= 30) CPWAIT(0); else CPWAIT(1);
        __syncthreads();     // tile kt visible + buffer (kt+2)%3 free

        if (kt + 2 < 32) { ISSUEKV((kt + 2) % 3, kt + 2); CPCOMMIT(); }

        const int st = kt % 3;

        float S[8][4];
#pragma unroll
        for (int i = 0; i < 8; i++)
#pragma unroll
            for (int j = 0; j < 4; j++) S[i][j] = 0.0f;

#pragma unroll
        for (int kh = 0; kh < 2; kh++) {
#pragma unroll
            for (int nh = 0; nh < 2; nh++) {
                uint32_t bk[4][4];
#pragma unroll
                for (int i4 = 0; i4 < 4; i4++) {
                    int in = nh * 4 + i4;
                    ldsm4(bk[i4], cvta_s(Ks + (st * 64 + in * 8 + (lane & 7)) * 72
                                            + kh * 32 + (lane >> 3) * 8));
                }
#pragma unroll
                for (int ks2 = 0; ks2 < 2; ks2++) {
#pragma unroll
                    for (int i4 = 0; i4 < 4; i4++)
                        mma16816(S[nh * 4 + i4], aq[kh * 2 + ks2], &bk[i4][ks2 * 2]);
                }
            }
        }

        float mx0 = -INFINITY, mx1 = -INFINITY;
#pragma unroll
        for (int in = 0; in < 8; in++) {
            mx0 = fmaxf(mx0, fmaxf(S[in][0], S[in][1]));
            mx1 = fmaxf(mx1, fmaxf(S[in][2], S[in][3]));
        }
        mx0 = fmaxf(mx0, __shfl_xor_sync(0xffffffffu, mx0, 1));
        mx0 = fmaxf(mx0, __shfl_xor_sync(0xffffffffu, mx0, 2));
        mx1 = fmaxf(mx1, __shfl_xor_sync(0xffffffffu, mx1, 1));
        mx1 = fmaxf(mx1, __shfl_xor_sync(0xffffffffu, mx1, 2));

        float nm0 = fmaxf(m0, mx0), nm1 = fmaxf(m1, mx1);
        float cor0 = ex2(m0 - nm0), cor1 = ex2(m1 - nm1);
        float sum0 = 0.0f, sum1 = 0.0f;
#pragma unroll
        for (int in = 0; in < 8; in++) {
            S[in][0] = ex2(S[in][0] - nm0);
            S[in][1] = ex2(S[in][1] - nm0);
            S[in][2] = ex2(S[in][2] - nm1);
            S[in][3] = ex2(S[in][3] - nm1);
            sum0 += S[in][0] + S[in][1];
            sum1 += S[in][2] + S[in][3];
        }
        sum0 += __shfl_xor_sync(0xffffffffu, sum0, 1);
        sum0 += __shfl_xor_sync(0xffffffffu, sum0, 2);
        sum1 += __shfl_xor_sync(0xffffffffu, sum1, 1);
        sum1 += __shfl_xor_sync(0xffffffffu, sum1, 2);
        l0 = l0 * cor0 + sum0;  m0 = nm0;
        l1 = l1 * cor1 + sum1;  m1 = nm1;
#pragma unroll
        for (int in = 0; in < 8; in++) {
            O[in][0] *= cor0; O[in][1] *= cor0;
            O[in][2] *= cor1; O[in][3] *= cor1;
        }

#pragma unroll
        for (int kj = 0; kj < 4; kj++) {
            uint32_t pa[4];
            pa[0] = pack_h2(S[2 * kj][0],     S[2 * kj][1]);
            pa[1] = pack_h2(S[2 * kj][2],     S[2 * kj][3]);
            pa[2] = pack_h2(S[2 * kj + 1][0], S[2 * kj + 1][1]);
            pa[3] = pack_h2(S[2 * kj + 1][2], S[2 * kj + 1][3]);
#pragma unroll
            for (int nv = 0; nv < 4; nv++) {
                uint32_t bv[4];
                ldsm4t(bv, cvta_s(Vs + (st * 64 + kj * 16 + ((lane >> 3) & 1) * 8
                                        + (lane & 7)) * 72 + nv * 16 + (lane >> 4) * 8));
                mma16816(O[nv * 2],     pa, &bv[0]);
                mma16816(O[nv * 2 + 1], pa, &bv[2]);
            }
        }
    }
#undef ISSUEKV

    float inv0 = 1.0f / l0, inv1 = 1.0f / l1;
    int nrow0 = q0 + warp * 16 + r;
    size_t base0 = ((size_t)b * Nn + nrow0) * DIM + h * DHd;
    size_t base1 = ((size_t)b * Nn + nrow0 + 8) * DIM + h * DHd;
#pragma unroll
    for (int nv = 0; nv < 8; nv++) {
        int col = nv * 8 + cq;
        *(__half2*)(Out + base0 + col) = __floats2half2_rn(O[nv][0] * inv0, O[nv][1] * inv0);
        *(__half2*)(Out + base1 + col) = __floats2half2_rn(O[nv][2] * inv1, O[nv][3] * inv1);
    }
}

// ---------------------------------------------------------------------------
extern "C" void kernel_launch(void* const* d_in, const int* in_sizes, int n_in,
                              void* d_out, int out_size)
{
    const float* x   = (const float*)d_in[0];
    const float* Wq  = (const float*)d_in[1];
    const float* Wk  = (const float*)d_in[2];
    const float* Wv  = (const float*)d_in[3];
    const float* Wo  = (const float*)d_in[4];
    const float* bo  = (const float*)d_in[5];
    const float* qsc = (const float*)d_in[6];
    const float* ksc = (const float*)d_in[7];
    float* out = (float*)d_out;

    __half *Xh, *Wqkvh, *Woh, *Qh, *Kh, *Vh, *AOh;
    cudaGetSymbolAddress((void**)&Xh,    g_Xh);
    cudaGetSymbolAddress((void**)&Wqkvh, g_Wqkvh);
    cudaGetSymbolAddress((void**)&Woh,   g_Woh);
    cudaGetSymbolAddress((void**)&Qh,    g_Qh);
    cudaGetSymbolAddress((void**)&Kh,    g_Kh);
    cudaGetSymbolAddress((void**)&Vh,    g_Vh);
    cudaGetSymbolAddress((void**)&AOh,   g_AOh);

    const int smem_g = 3 * GSTG;                               // 92160
    const int smem_f = (128 * 72 + 6 * 64 * 72) * sizeof(__half);  // 73728
    cudaFuncSetAttribute(hgemm2<0>, cudaFuncAttributeMaxDynamicSharedMemorySize, smem_g);
    cudaFuncSetAttribute(hgemm2<1>, cudaFuncAttributeMaxDynamicSharedMemorySize, smem_g);
    cudaFuncSetAttribute(flash_h,   cudaFuncAttributeMaxDynamicSharedMemorySize, smem_f);

    convert_all<<<4096, 256>>>(x, Wq, Wk, Wv, Wo, Xh, Wqkvh, Woh);

    // fused QKV projection + QK norm: N = 3072 in 256-wide tiles
    hgemm2<1><<<dim3(3 * DIM / 256, Mrows / 128), 256, smem_g>>>(
        Xh, Wqkvh, nullptr, nullptr, Qh, Kh, Vh, qsc, ksc);

    flash_h<<<dim3(Nn / 128, BHh), 256, smem_f>>>(Qh, Kh, Vh, AOh);

    // output projection
    hgemm2<0><<<dim3(DIM / 256, Mrows / 128), 256, smem_g>>>(
        AOh, Woh, bo, out, nullptr, nullptr, nullptr, nullptr, nullptr);
}

// round 7
// speedup vs baseline: 7.5094x; 1.0696x over previous
#include <cuda_runtime.h>
#include <cuda_fp16.h>
#include <math.h>
#include <stdint.h>

#define Bb   2
#define Nn   2048
#define DIM  1024
#define Hh   16
#define DHd  64
#define Mrows (Bb * Nn)          // 4096
#define BHh  (Bb * Hh)           // 32
#define QMULT 0.18033688011112042f   // 0.125 * log2(e)

// fp16 scratch (device globals)
__device__ __half g_Xh[Mrows * DIM];
__device__ __half g_Wqkvh[3 * DIM * DIM];
__device__ __half g_Woh[DIM * DIM];
__device__ __half g_Qh[BHh * Nn * DHd];
__device__ __half g_Kh[BHh * Nn * DHd];
__device__ __half g_Vh[BHh * Nn * DHd];
__device__ __half g_AOh[Mrows * DIM];

// ---------------------------------------------------------------------------
__device__ __forceinline__ uint32_t cvta_s(const void* p) {
    return (uint32_t)__cvta_generic_to_shared(p);
}
__device__ __forceinline__ void ldsm4(uint32_t* r, uint32_t a) {
    asm volatile("ldmatrix.sync.aligned.m8n8.x4.shared.b16 {%0,%1,%2,%3}, [%4];"
                 : "=r"(r[0]), "=r"(r[1]), "=r"(r[2]), "=r"(r[3]) : "r"(a));
}
__device__ __forceinline__ void ldsm4t(uint32_t* r, uint32_t a) {
    asm volatile("ldmatrix.sync.aligned.m8n8.x4.trans.shared.b16 {%0,%1,%2,%3}, [%4];"
                 : "=r"(r[0]), "=r"(r[1]), "=r"(r[2]), "=r"(r[3]) : "r"(a));
}
__device__ __forceinline__ void mma16816(float* c, const uint32_t* a, const uint32_t* b) {
    asm volatile("mma.sync.aligned.m16n8k16.row.col.f32.f16.f16.f32 "
                 "{%0,%1,%2,%3}, {%4,%5,%6,%7}, {%8,%9}, {%0,%1,%2,%3};"
                 : "+f"(c[0]), "+f"(c[1]), "+f"(c[2]), "+f"(c[3])
                 : "r"(a[0]), "r"(a[1]), "r"(a[2]), "r"(a[3]), "r"(b[0]), "r"(b[1]));
}
__device__ __forceinline__ uint32_t pack_h2(float a, float b) {
    __half2 h = __floats2half2_rn(a, b);
    return *reinterpret_cast<uint32_t*>(&h);
}
__device__ __forceinline__ float ex2(float x) {
    float y;
    asm("ex2.approx.ftz.f32 %0, %1;" : "=f"(y) : "f"(x));
    return y;
}

#define CP16(dst, src) asm volatile("cp.async.cg.shared.global [%0], [%1], 16;" \
                                    :: "r"(dst), "l"(src))
#define CPCOMMIT() asm volatile("cp.async.commit_group;")
#define CPWAIT(N)  asm volatile("cp.async.wait_group %0;" :: "n"(N))

// ---------------------------------------------------------------------------
// merged fp32 -> fp16 conversion: x, Wq, Wk, Wv, Wo in one launch (unit = 8 floats)
// ---------------------------------------------------------------------------
__global__ __launch_bounds__(256)
void convert_all(const float* __restrict__ x,  const float* __restrict__ Wq,
                 const float* __restrict__ Wk, const float* __restrict__ Wv,
                 const float* __restrict__ Wo,
                 __half* __restrict__ Xh, __half* __restrict__ Wqkvh,
                 __half* __restrict__ Woh)
{
    int i = blockIdx.x * 256 + threadIdx.x;     // 0 .. 1048575
    const float* src;
    __half* dst;
    int j = i;
    if (j < 524288)      { src = x;  dst = Xh; }
    else {
        j -= 524288;
        if (j < 131072)      { src = Wq; dst = Wqkvh; }
        else { j -= 131072;
            if (j < 131072)  { src = Wk; dst = Wqkvh + 1048576; }
            else { j -= 131072;
                if (j < 131072) { src = Wv; dst = Wqkvh + 2097152; }
                else { j -= 131072; src = Wo; dst = Woh; }
            }
        }
    }
    float4 a = ((const float4*)src)[2 * j];
    float4 b = ((const float4*)src)[2 * j + 1];
    __half2 h[4] = { __floats2half2_rn(a.x, a.y), __floats2half2_rn(a.z, a.w),
                     __floats2half2_rn(b.x, b.y), __floats2half2_rn(b.z, b.w) };
    ((int4*)dst)[j] = *reinterpret_cast<int4*>(h);
}

// ---------------------------------------------------------------------------
// fp16 HMMA GEMM: C[m,e] = sum_k A[m,k]*B[e,k], K=1024.
// CTA 128x128, BK=32, 3-stage cp.async, single sync/iter.
// 8 warps as 4(M) x 2(N): warp tile 32x64. 2 CTAs/SM (launch_bounds).
// EPI 0: fp32 out + bias. EPI 1: QKV demux + fused per-head L2 norm.
// ---------------------------------------------------------------------------
#define GSTG 20480           // bytes/stage: A 128*80 + B 128*80

template <int EPI>
__global__ __launch_bounds__(256, 2)
void hgemm3(const __half* __restrict__ A, const __half* __restrict__ B,
            const float* __restrict__ bias, float* __restrict__ Cf,
            __half* __restrict__ Qo, __half* __restrict__ Ko, __half* __restrict__ Vo,
            const float* __restrict__ qsc, const float* __restrict__ ksc)
{
    extern __shared__ __align__(16) char gsm[];
    const uint32_t sb = cvta_s(gsm);

    const int tid = threadIdx.x;
    const int warp = tid >> 5, lane = tid & 31;
    const int bm = blockIdx.y * 128, bn = blockIdx.x * 128;
    const int wm = (warp >> 1) * 32, wn = (warp & 1) * 64;

    float c[2][8][4];
#pragma unroll
    for (int i = 0; i < 2; i++)
#pragma unroll
        for (int j = 0; j < 8; j++)
#pragma unroll
            for (int q = 0; q < 4; q++) c[i][j][q] = 0.0f;

#define GISSUE(S, KB)                                                          \
    do {                                                                       \
        uint32_t As = sb + (S) * GSTG;                                         \
        uint32_t Bs = As + 10240;                                              \
        _Pragma("unroll")                                                      \
        for (int it = 0; it < 2; it++) {                                       \
            int id = it * 256 + tid;                                           \
            int m = id >> 2, c4 = id & 3;                                      \
            CP16(As + m * 80 + c4 * 16,                                        \
                 A + (size_t)(bm + m) * 1024 + (KB) + c4 * 8);                 \
            CP16(Bs + m * 80 + c4 * 16,                                        \
                 B + (size_t)(bn + m) * 1024 + (KB) + c4 * 8);                 \
        }                                                                      \
    } while (0)

    GISSUE(0, 0);  CPCOMMIT();
    GISSUE(1, 32); CPCOMMIT();

    for (int kt = 0; kt < 32; kt++) {
        if (kt >= 30) CPWAIT(0); else CPWAIT(1);
        __syncthreads();     // stage kt visible + stage (kt+2)%3 free

        if (kt + 2 < 32) { GISSUE((kt + 2) % 3, (kt + 2) * 32); CPCOMMIT(); }

        const uint32_t As = sb + (kt % 3) * GSTG;
        const uint32_t Bs = As + 10240;

        uint32_t b[8][4];
#pragma unroll
        for (int in = 0; in < 8; in++)
            ldsm4(b[in], Bs + (wn + in * 8 + (lane & 7)) * 80 + (lane >> 3) * 16);
#pragma unroll
        for (int ks = 0; ks < 2; ks++) {
            uint32_t a[2][4];
#pragma unroll
            for (int im = 0; im < 2; im++)
                ldsm4(a[im], As + (wm + im * 16 + (lane & 15)) * 80
                               + ks * 32 + (lane >> 4) * 16);
#pragma unroll
            for (int im = 0; im < 2; im++)
#pragma unroll
                for (int in = 0; in < 8; in++)
                    mma16816(c[im][in], a[im], &b[in][ks * 2]);
        }
    }
#undef GISSUE

    // ---- epilogue ----
    const int r = lane >> 2, cq = (lane & 3) * 2;

    if (EPI == 0) {
        float2 bi[8];
#pragma unroll
        for (int in = 0; in < 8; in++)
            bi[in] = *(const float2*)&bias[bn + wn + in * 8 + cq];
#pragma unroll
        for (int im = 0; im < 2; im++)
#pragma unroll
            for (int hm = 0; hm < 2; hm++) {
                int m = bm + wm + im * 16 + hm * 8 + r;
#pragma unroll
                for (int in = 0; in < 8; in++) {
                    int e = bn + wn + in * 8 + cq;
                    *(float2*)&Cf[(size_t)m * 1024 + e] =
                        make_float2(c[im][in][hm * 2] + bi[in].x,
                                    c[im][in][hm * 2 + 1] + bi[in].y);
                }
            }
    } else {
        const int which = bn >> 10;                  // 0=Q 1=K 2=V
        const int bnl = bn & 1023;
        __half* dst = (which == 0) ? Qo : (which == 1) ? Ko : Vo;
        const int h = (bnl + wn) >> 6;               // warp N-tile = one head
        const float mult = (which == 0) ? QMULT : 1.0f;
        const float* sc = (which == 0) ? qsc : ksc;

        float2 s2[8];
        if (which < 2) {
#pragma unroll
            for (int in = 0; in < 8; in++)
                s2[in] = *(const float2*)&sc[h * 64 + in * 8 + cq];
        } else {
#pragma unroll
            for (int in = 0; in < 8; in++) s2[in] = make_float2(1.0f, 1.0f);
        }

#pragma unroll
        for (int im = 0; im < 2; im++)
#pragma unroll
            for (int hm = 0; hm < 2; hm++) {
                float inv = 1.0f;
                if (which < 2) {
                    float ss = 0.0f;
#pragma unroll
                    for (int in = 0; in < 8; in++)
                        ss += c[im][in][hm * 2] * c[im][in][hm * 2]
                            + c[im][in][hm * 2 + 1] * c[im][in][hm * 2 + 1];
                    ss += __shfl_xor_sync(0xffffffffu, ss, 1);
                    ss += __shfl_xor_sync(0xffffffffu, ss, 2);
                    inv = mult / fmaxf(sqrtf(ss), 1e-12f);
                }
                int m = bm + wm + im * 16 + hm * 8 + r;
                int bbq = m >> 11, n = m & 2047;
                __half* row = dst + (size_t)(((bbq * Hh + h) * Nn) + n) * DHd;
#pragma unroll
                for (int in = 0; in < 8; in++) {
                    int dh = in * 8 + cq;
                    *(__half2*)&row[dh] = __floats2half2_rn(
                        c[im][in][hm * 2] * inv * s2[in].x,
                        c[im][in][hm * 2 + 1] * inv * s2[in].y);
                }
            }
    }
}

// ---------------------------------------------------------------------------
// Flash attention, fp16 MMA + fp32 accum, triple-buffered K/V, 2 CTAs/SM.
// CTA: 128 queries of one (b,h); 8 warps * 16 rows; 64-key tiles, 32 tiles.
// ---------------------------------------------------------------------------
__global__ __launch_bounds__(256, 2)
void flash_h(const __half* __restrict__ Q, const __half* __restrict__ K,
             const __half* __restrict__ V, __half* __restrict__ Out)
{
    extern __shared__ __half fsm[];
    __half* Qs = fsm;                        // [128][72]
    __half* Ks = fsm + 128 * 72;             // [3][64][72]
    __half* Vs = Ks + 3 * 64 * 72;           // [3][64][72]

    const int tid = threadIdx.x;
    const int warp = tid >> 5, lane = tid & 31;
    const int bh = blockIdx.y;
    const int q0 = blockIdx.x * 128;
    const int b = bh >> 4, h = bh & 15;
    const int r = lane >> 2, cq = (lane & 3) * 2;

    const __half* Qg = Q + ((size_t)bh * Nn + q0) * DHd;
#pragma unroll
    for (int it = 0; it < 4; it++) {
        int id = it * 256 + tid;
        int m = id >> 3, cc = (id & 7) * 8;
        *(int4*)&Qs[m * 72 + cc] = *(const int4*)(Qg + m * DHd + cc);
    }

    const __half* Kg = K + (size_t)bh * Nn * DHd;
    const __half* Vg = V + (size_t)bh * Nn * DHd;

#define ISSUEKV(S, KT)                                                         \
    do {                                                                       \
        _Pragma("unroll")                                                      \
        for (int i = 0; i < 2; i++) {                                          \
            int id = i * 256 + tid;                                            \
            int m = id >> 3, cc = (id & 7) * 8;                                \
            size_t go = (size_t)((KT) * 64 + m) * DHd + cc;                    \
            CP16(cvta_s(Ks + ((S) * 64 + m) * 72 + cc), Kg + go);              \
            CP16(cvta_s(Vs + ((S) * 64 + m) * 72 + cc), Vg + go);              \
        }                                                                      \
    } while (0)

    ISSUEKV(0, 0); CPCOMMIT();
    ISSUEKV(1, 1); CPCOMMIT();
    __syncthreads();                         // Qs visible

    uint32_t aq[4][4];                       // hoisted Q fragments
#pragma unroll
    for (int kq = 0; kq < 4; kq++)
        ldsm4(aq[kq], cvta_s(Qs + (warp * 16 + (lane & 15)) * 72
                                + kq * 16 + (lane >> 4) * 8));

    float O[8][4];
#pragma unroll
    for (int i = 0; i < 8; i++)
#pragma unroll
        for (int j = 0; j < 4; j++) O[i][j] = 0.0f;
    float m0 = -INFINITY, m1 = -INFINITY, l0 = 0.0f, l1 = 0.0f;

    for (int kt = 0; kt < 32; kt++) {
        if (kt >= 30) CPWAIT(0); else CPWAIT(1);
        __syncthreads();

        if (kt + 2 < 32) { ISSUEKV((kt + 2) % 3, kt + 2); CPCOMMIT(); }

        const int st = kt % 3;

        float S[8][4];
#pragma unroll
        for (int i = 0; i < 8; i++)
#pragma unroll
            for (int j = 0; j < 4; j++) S[i][j] = 0.0f;

        // S = Q K^T — load one K fragment at a time (register diet)
#pragma unroll
        for (int kh = 0; kh < 2; kh++) {
#pragma unroll
            for (int in = 0; in < 8; in++) {
                uint32_t bk[4];
                ldsm4(bk, cvta_s(Ks + (st * 64 + in * 8 + (lane & 7)) * 72
                                    + kh * 32 + (lane >> 3) * 8));
                mma16816(S[in], aq[kh * 2],     &bk[0]);
                mma16816(S[in], aq[kh * 2 + 1], &bk[2]);
            }
        }

        float mx0 = -INFINITY, mx1 = -INFINITY;
#pragma unroll
        for (int in = 0; in < 8; in++) {
            mx0 = fmaxf(mx0, fmaxf(S[in][0], S[in][1]));
            mx1 = fmaxf(mx1, fmaxf(S[in][2], S[in][3]));
        }
        mx0 = fmaxf(mx0, __shfl_xor_sync(0xffffffffu, mx0, 1));
        mx0 = fmaxf(mx0, __shfl_xor_sync(0xffffffffu, mx0, 2));
        mx1 = fmaxf(mx1, __shfl_xor_sync(0xffffffffu, mx1, 1));
        mx1 = fmaxf(mx1, __shfl_xor_sync(0xffffffffu, mx1, 2));

        float nm0 = fmaxf(m0, mx0), nm1 = fmaxf(m1, mx1);
        float cor0 = ex2(m0 - nm0), cor1 = ex2(m1 - nm1);
        float sum0 = 0.0f, sum1 = 0.0f;
#pragma unroll
        for (int in = 0; in < 8; in++) {
            S[in][0] = ex2(S[in][0] - nm0);
            S[in][1] = ex2(S[in][1] - nm0);
            S[in][2] = ex2(S[in][2] - nm1);
            S[in][3] = ex2(S[in][3] - nm1);
            sum0 += S[in][0] + S[in][1];
            sum1 += S[in][2] + S[in][3];
        }
        sum0 += __shfl_xor_sync(0xffffffffu, sum0, 1);
        sum0 += __shfl_xor_sync(0xffffffffu, sum0, 2);
        sum1 += __shfl_xor_sync(0xffffffffu, sum1, 1);
        sum1 += __shfl_xor_sync(0xffffffffu, sum1, 2);
        l0 = l0 * cor0 + sum0;  m0 = nm0;
        l1 = l1 * cor1 + sum1;  m1 = nm1;
#pragma unroll
        for (int in = 0; in < 8; in++) {
            O[in][0] *= cor0; O[in][1] *= cor0;
            O[in][2] *= cor1; O[in][3] *= cor1;
        }

#pragma unroll
        for (int kj = 0; kj < 4; kj++) {
            uint32_t pa[4];
            pa[0] = pack_h2(S[2 * kj][0],     S[2 * kj][1]);
            pa[1] = pack_h2(S[2 * kj][2],     S[2 * kj][3]);
            pa[2] = pack_h2(S[2 * kj + 1][0], S[2 * kj + 1][1]);
            pa[3] = pack_h2(S[2 * kj + 1][2], S[2 * kj + 1][3]);
#pragma unroll
            for (int nv = 0; nv < 4; nv++) {
                uint32_t bv[4];
                ldsm4t(bv, cvta_s(Vs + (st * 64 + kj * 16 + ((lane >> 3) & 1) * 8
                                        + (lane & 7)) * 72 + nv * 16 + (lane >> 4) * 8));
                mma16816(O[nv * 2],     pa, &bv[0]);
                mma16816(O[nv * 2 + 1], pa, &bv[2]);
            }
        }
    }
#undef ISSUEKV

    float inv0 = 1.0f / l0, inv1 = 1.0f / l1;
    int nrow0 = q0 + warp * 16 + r;
    size_t base0 = ((size_t)b * Nn + nrow0) * DIM + h * DHd;
    size_t base1 = ((size_t)b * Nn + nrow0 + 8) * DIM + h * DHd;
#pragma unroll
    for (int nv = 0; nv < 8; nv++) {
        int col = nv * 8 + cq;
        *(__half2*)(Out + base0 + col) = __floats2half2_rn(O[nv][0] * inv0, O[nv][1] * inv0);
        *(__half2*)(Out + base1 + col) = __floats2half2_rn(O[nv][2] * inv1, O[nv][3] * inv1);
    }
}

// ---------------------------------------------------------------------------
extern "C" void kernel_launch(void* const* d_in, const int* in_sizes, int n_in,
                              void* d_out, int out_size)
{
    const float* x   = (const float*)d_in[0];
    const float* Wq  = (const float*)d_in[1];
    const float* Wk  = (const float*)d_in[2];
    const float* Wv  = (const float*)d_in[3];
    const float* Wo  = (const float*)d_in[4];
    const float* bo  = (const float*)d_in[5];
    const float* qsc = (const float*)d_in[6];
    const float* ksc = (const float*)d_in[7];
    float* out = (float*)d_out;

    __half *Xh, *Wqkvh, *Woh, *Qh, *Kh, *Vh, *AOh;
    cudaGetSymbolAddress((void**)&Xh,    g_Xh);
    cudaGetSymbolAddress((void**)&Wqkvh, g_Wqkvh);
    cudaGetSymbolAddress((void**)&Woh,   g_Woh);
    cudaGetSymbolAddress((void**)&Qh,    g_Qh);
    cudaGetSymbolAddress((void**)&Kh,    g_Kh);
    cudaGetSymbolAddress((void**)&Vh,    g_Vh);
    cudaGetSymbolAddress((void**)&AOh,   g_AOh);

    const int smem_g = 3 * GSTG;                                   // 61440
    const int smem_f = (128 * 72 + 6 * 64 * 72) * sizeof(__half);  // 73728
    cudaFuncSetAttribute(hgemm3<0>, cudaFuncAttributeMaxDynamicSharedMemorySize, smem_g);
    cudaFuncSetAttribute(hgemm3<1>, cudaFuncAttributeMaxDynamicSharedMemorySize, smem_g);
    cudaFuncSetAttribute(flash_h,   cudaFuncAttributeMaxDynamicSharedMemorySize, smem_f);

    convert_all<<<4096, 256>>>(x, Wq, Wk, Wv, Wo, Xh, Wqkvh, Woh);

    // fused QKV projection + QK norm: N = 3072 in 128-wide tiles
    hgemm3<1><<<dim3(3 * DIM / 128, Mrows / 128), 256, smem_g>>>(
        Xh, Wqkvh, nullptr, nullptr, Qh, Kh, Vh, qsc, ksc);

    flash_h<<<dim3(Nn / 128, BHh), 256, smem_f>>>(Qh, Kh, Vh, AOh);

    // output projection
    hgemm3<0><<<dim3(DIM / 128, Mrows / 128), 256, smem_g>>>(
        AOh, Woh, bo, out, nullptr, nullptr, nullptr, nullptr, nullptr);
}

// round 8
// speedup vs baseline: 7.8175x; 1.0410x over previous
#include <cuda_runtime.h>
#include <cuda_fp16.h>
#include <math.h>
#include <stdint.h>

#define Bb   2
#define Nn   2048
#define DIM  1024
#define Hh   16
#define DHd  64
#define Mrows (Bb * Nn)          // 4096
#define BHh  (Bb * Hh)           // 32
#define QMULT 0.18033688011112042f   // 0.125 * log2(e)

// fp16 scratch (device globals)
__device__ __half g_Xh[Mrows * DIM];
__device__ __half g_Wqkvh[3 * DIM * DIM];
__device__ __half g_Woh[DIM * DIM];
__device__ __half g_Qh[BHh * Nn * DHd];
__device__ __half g_Kh[BHh * Nn * DHd];
__device__ __half g_Vh[BHh * Nn * DHd];
__device__ __half g_AOh[Mrows * DIM];

// ---------------------------------------------------------------------------
__device__ __forceinline__ uint32_t cvta_s(const void* p) {
    return (uint32_t)__cvta_generic_to_shared(p);
}
__device__ __forceinline__ void ldsm4(uint32_t* r, uint32_t a) {
    asm volatile("ldmatrix.sync.aligned.m8n8.x4.shared.b16 {%0,%1,%2,%3}, [%4];"
                 : "=r"(r[0]), "=r"(r[1]), "=r"(r[2]), "=r"(r[3]) : "r"(a));
}
__device__ __forceinline__ void ldsm4t(uint32_t* r, uint32_t a) {
    asm volatile("ldmatrix.sync.aligned.m8n8.x4.trans.shared.b16 {%0,%1,%2,%3}, [%4];"
                 : "=r"(r[0]), "=r"(r[1]), "=r"(r[2]), "=r"(r[3]) : "r"(a));
}
__device__ __forceinline__ void mma16816(float* c, const uint32_t* a, const uint32_t* b) {
    asm volatile("mma.sync.aligned.m16n8k16.row.col.f32.f16.f16.f32 "
                 "{%0,%1,%2,%3}, {%4,%5,%6,%7}, {%8,%9}, {%0,%1,%2,%3};"
                 : "+f"(c[0]), "+f"(c[1]), "+f"(c[2]), "+f"(c[3])
                 : "r"(a[0]), "r"(a[1]), "r"(a[2]), "r"(a[3]), "r"(b[0]), "r"(b[1]));
}
__device__ __forceinline__ uint32_t pack_h2(float a, float b) {
    __half2 h = __floats2half2_rn(a, b);
    return *reinterpret_cast<uint32_t*>(&h);
}
__device__ __forceinline__ float ex2(float x) {
    float y;
    asm("ex2.approx.ftz.f32 %0, %1;" : "=f"(y) : "f"(x));
    return y;
}

#define CP16(dst, src) asm volatile("cp.async.cg.shared.global [%0], [%1], 16;" \
                                    :: "r"(dst), "l"(src))
#define CPCOMMIT() asm volatile("cp.async.commit_group;")
#define CPWAIT(N)  asm volatile("cp.async.wait_group %0;" :: "n"(N))

// ---------------------------------------------------------------------------
// merged fp32 -> fp16 conversion (unit = 8 floats)
// ---------------------------------------------------------------------------
__global__ __launch_bounds__(256)
void convert_all(const float* __restrict__ x,  const float* __restrict__ Wq,
                 const float* __restrict__ Wk, const float* __restrict__ Wv,
                 const float* __restrict__ Wo,
                 __half* __restrict__ Xh, __half* __restrict__ Wqkvh,
                 __half* __restrict__ Woh)
{
    int i = blockIdx.x * 256 + threadIdx.x;     // 0 .. 1048575
    const float* src;
    __half* dst;
    int j = i;
    if (j < 524288)      { src = x;  dst = Xh; }
    else {
        j -= 524288;
        if (j < 131072)      { src = Wq; dst = Wqkvh; }
        else { j -= 131072;
            if (j < 131072)  { src = Wk; dst = Wqkvh + 1048576; }
            else { j -= 131072;
                if (j < 131072) { src = Wv; dst = Wqkvh + 2097152; }
                else { j -= 131072; src = Wo; dst = Woh; }
            }
        }
    }
    float4 a = ((const float4*)src)[2 * j];
    float4 b = ((const float4*)src)[2 * j + 1];
    __half2 h[4] = { __floats2half2_rn(a.x, a.y), __floats2half2_rn(a.z, a.w),
                     __floats2half2_rn(b.x, b.y), __floats2half2_rn(b.z, b.w) };
    ((int4*)dst)[j] = *reinterpret_cast<int4*>(h);
}

// ---------------------------------------------------------------------------
// fp16 HMMA GEMM: C[m,e] = sum_k A[m,k]*B[e,k], K=1024.
// CTA 128x128, BK=64 (16 iters), 2-stage cp.async, 1 barrier/iter.
// 8 warps as 4(M) x 2(N): warp tile 32x64, 64 mma/iter. 2 CTAs/SM.
// smem row pitch 144 B (72 halves): 16B-aligned, conflict-free ldsm.
// EPI 0: fp32 out + bias. EPI 1: QKV demux + fused per-head L2 norm.
// ---------------------------------------------------------------------------
#define GSTG2 36864          // stage bytes: (128 A rows + 128 B rows) * 144

template <int EPI>
__global__ __launch_bounds__(256, 2)
void hgemm4(const __half* __restrict__ A, const __half* __restrict__ B,
            const float* __restrict__ bias, float* __restrict__ Cf,
            __half* __restrict__ Qo, __half* __restrict__ Ko, __half* __restrict__ Vo,
            const float* __restrict__ qsc, const float* __restrict__ ksc)
{
    extern __shared__ __align__(16) char gsm[];
    const uint32_t sb = cvta_s(gsm);

    const int tid = threadIdx.x;
    const int warp = tid >> 5, lane = tid & 31;
    const int bm = blockIdx.y * 128, bn = blockIdx.x * 128;
    const int wm = (warp >> 1) * 32, wn = (warp & 1) * 64;

    float c[2][8][4];
#pragma unroll
    for (int i = 0; i < 2; i++)
#pragma unroll
        for (int j = 0; j < 8; j++)
#pragma unroll
            for (int q = 0; q < 4; q++) c[i][j][q] = 0.0f;

    // stage layout: A rows [0,128) then B rows [0,128), pitch 144 B
#define GISSUE(S, KB)                                                          \
    do {                                                                       \
        uint32_t As = sb + (S) * GSTG2;                                        \
        uint32_t Bs = As + 18432;                                              \
        _Pragma("unroll")                                                      \
        for (int it = 0; it < 4; it++) {                                       \
            int id = it * 256 + tid;                                           \
            int m = id >> 3, c8 = id & 7;                                      \
            CP16(As + m * 144 + c8 * 16,                                       \
                 A + (size_t)(bm + m) * 1024 + (KB) + c8 * 8);                 \
            CP16(Bs + m * 144 + c8 * 16,                                       \
                 B + (size_t)(bn + m) * 1024 + (KB) + c8 * 8);                 \
        }                                                                      \
    } while (0)

    GISSUE(0, 0); CPCOMMIT();

    for (int kt = 0; kt < 16; kt++) {
        CPWAIT(0);
        __syncthreads();     // stage kt ready; buffer (kt+1)&1 drained by all warps

        if (kt + 1 < 16) { GISSUE((kt + 1) & 1, (kt + 1) * 64); CPCOMMIT(); }

        const uint32_t As = sb + (kt & 1) * GSTG2;
        const uint32_t Bs = As + 18432;

#pragma unroll
        for (int s = 0; s < 2; s++) {            // two k32 halves of BK=64
            uint32_t b[8][4];
#pragma unroll
            for (int in = 0; in < 8; in++)
                ldsm4(b[in], Bs + (wn + in * 8 + (lane & 7)) * 144
                               + s * 64 + (lane >> 3) * 16);
#pragma unroll
            for (int ks = 0; ks < 2; ks++) {
                uint32_t a[2][4];
#pragma unroll
                for (int im = 0; im < 2; im++)
                    ldsm4(a[im], As + (wm + im * 16 + (lane & 15)) * 144
                                   + s * 64 + ks * 32 + (lane >> 4) * 16);
#pragma unroll
                for (int im = 0; im < 2; im++)
#pragma unroll
                    for (int in = 0; in < 8; in++)
                        mma16816(c[im][in], a[im], &b[in][ks * 2]);
            }
        }
    }
#undef GISSUE

    // ---- epilogue ----
    const int r = lane >> 2, cq = (lane & 3) * 2;

    if (EPI == 0) {
        float2 bi[8];
#pragma unroll
        for (int in = 0; in < 8; in++)
            bi[in] = *(const float2*)&bias[bn + wn + in * 8 + cq];
#pragma unroll
        for (int im = 0; im < 2; im++)
#pragma unroll
            for (int hm = 0; hm < 2; hm++) {
                int m = bm + wm + im * 16 + hm * 8 + r;
#pragma unroll
                for (int in = 0; in < 8; in++) {
                    int e = bn + wn + in * 8 + cq;
                    *(float2*)&Cf[(size_t)m * 1024 + e] =
                        make_float2(c[im][in][hm * 2] + bi[in].x,
                                    c[im][in][hm * 2 + 1] + bi[in].y);
                }
            }
    } else {
        const int which = bn >> 10;                  // 0=Q 1=K 2=V
        const int bnl = bn & 1023;
        __half* dst = (which == 0) ? Qo : (which == 1) ? Ko : Vo;
        const int h = (bnl + wn) >> 6;               // warp N-tile = one head
        const float mult = (which == 0) ? QMULT : 1.0f;
        const float* sc = (which == 0) ? qsc : ksc;

        float2 s2[8];
        if (which < 2) {
#pragma unroll
            for (int in = 0; in < 8; in++)
                s2[in] = *(const float2*)&sc[h * 64 + in * 8 + cq];
        } else {
#pragma unroll
            for (int in = 0; in < 8; in++) s2[in] = make_float2(1.0f, 1.0f);
        }

#pragma unroll
        for (int im = 0; im < 2; im++)
#pragma unroll
            for (int hm = 0; hm < 2; hm++) {
                float inv = 1.0f;
                if (which < 2) {
                    float ss = 0.0f;
#pragma unroll
                    for (int in = 0; in < 8; in++)
                        ss += c[im][in][hm * 2] * c[im][in][hm * 2]
                            + c[im][in][hm * 2 + 1] * c[im][in][hm * 2 + 1];
                    ss += __shfl_xor_sync(0xffffffffu, ss, 1);
                    ss += __shfl_xor_sync(0xffffffffu, ss, 2);
                    inv = mult / fmaxf(sqrtf(ss), 1e-12f);
                }
                int m = bm + wm + im * 16 + hm * 8 + r;
                int bbq = m >> 11, n = m & 2047;
                __half* row = dst + (size_t)(((bbq * Hh + h) * Nn) + n) * DHd;
#pragma unroll
                for (int in = 0; in < 8; in++) {
                    int dh = in * 8 + cq;
                    *(__half2*)&row[dh] = __floats2half2_rn(
                        c[im][in][hm * 2] * inv * s2[in].x,
                        c[im][in][hm * 2 + 1] * inv * s2[in].y);
                }
            }
    }
}

// ---------------------------------------------------------------------------
// Flash attention (round-7 config: triple-buffered K/V, 2 CTAs/SM)
// ---------------------------------------------------------------------------
__global__ __launch_bounds__(256, 2)
void flash_h(const __half* __restrict__ Q, const __half* __restrict__ K,
             const __half* __restrict__ V, __half* __restrict__ Out)
{
    extern __shared__ __half fsm[];
    __half* Qs = fsm;                        // [128][72]
    __half* Ks = fsm + 128 * 72;             // [3][64][72]
    __half* Vs = Ks + 3 * 64 * 72;           // [3][64][72]

    const int tid = threadIdx.x;
    const int warp = tid >> 5, lane = tid & 31;
    const int bh = blockIdx.y;
    const int q0 = blockIdx.x * 128;
    const int b = bh >> 4, h = bh & 15;
    const int r = lane >> 2, cq = (lane & 3) * 2;

    const __half* Qg = Q + ((size_t)bh * Nn + q0) * DHd;
#pragma unroll
    for (int it = 0; it < 4; it++) {
        int id = it * 256 + tid;
        int m = id >> 3, cc = (id & 7) * 8;
        *(int4*)&Qs[m * 72 + cc] = *(const int4*)(Qg + m * DHd + cc);
    }

    const __half* Kg = K + (size_t)bh * Nn * DHd;
    const __half* Vg = V + (size_t)bh * Nn * DHd;

#define ISSUEKV(S, KT)                                                         \
    do {                                                                       \
        _Pragma("unroll")                                                      \
        for (int i = 0; i < 2; i++) {                                          \
            int id = i * 256 + tid;                                            \
            int m = id >> 3, cc = (id & 7) * 8;                                \
            size_t go = (size_t)((KT) * 64 + m) * DHd + cc;                    \
            CP16(cvta_s(Ks + ((S) * 64 + m) * 72 + cc), Kg + go);              \
            CP16(cvta_s(Vs + ((S) * 64 + m) * 72 + cc), Vg + go);              \
        }                                                                      \
    } while (0)

    ISSUEKV(0, 0); CPCOMMIT();
    ISSUEKV(1, 1); CPCOMMIT();
    __syncthreads();                         // Qs visible

    uint32_t aq[4][4];                       // hoisted Q fragments
#pragma unroll
    for (int kq = 0; kq < 4; kq++)
        ldsm4(aq[kq], cvta_s(Qs + (warp * 16 + (lane & 15)) * 72
                                + kq * 16 + (lane >> 4) * 8));

    float O[8][4];
#pragma unroll
    for (int i = 0; i < 8; i++)
#pragma unroll
        for (int j = 0; j < 4; j++) O[i][j] = 0.0f;
    float m0 = -INFINITY, m1 = -INFINITY, l0 = 0.0f, l1 = 0.0f;

    for (int kt = 0; kt < 32; kt++) {
        if (kt >= 30) CPWAIT(0); else CPWAIT(1);
        __syncthreads();

        if (kt + 2 < 32) { ISSUEKV((kt + 2) % 3, kt + 2); CPCOMMIT(); }

        const int st = kt % 3;

        float S[8][4];
#pragma unroll
        for (int i = 0; i < 8; i++)
#pragma unroll
            for (int j = 0; j < 4; j++) S[i][j] = 0.0f;

#pragma unroll
        for (int kh = 0; kh < 2; kh++) {
#pragma unroll
            for (int in = 0; in < 8; in++) {
                uint32_t bk[4];
                ldsm4(bk, cvta_s(Ks + (st * 64 + in * 8 + (lane & 7)) * 72
                                    + kh * 32 + (lane >> 3) * 8));
                mma16816(S[in], aq[kh * 2],     &bk[0]);
                mma16816(S[in], aq[kh * 2 + 1], &bk[2]);
            }
        }

        float mx0 = -INFINITY, mx1 = -INFINITY;
#pragma unroll
        for (int in = 0; in < 8; in++) {
            mx0 = fmaxf(mx0, fmaxf(S[in][0], S[in][1]));
            mx1 = fmaxf(mx1, fmaxf(S[in][2], S[in][3]));
        }
        mx0 = fmaxf(mx0, __shfl_xor_sync(0xffffffffu, mx0, 1));
        mx0 = fmaxf(mx0, __shfl_xor_sync(0xffffffffu, mx0, 2));
        mx1 = fmaxf(mx1, __shfl_xor_sync(0xffffffffu, mx1, 1));
        mx1 = fmaxf(mx1, __shfl_xor_sync(0xffffffffu, mx1, 2));

        float nm0 = fmaxf(m0, mx0), nm1 = fmaxf(m1, mx1);
        float cor0 = ex2(m0 - nm0), cor1 = ex2(m1 - nm1);
        float sum0 = 0.0f, sum1 = 0.0f;
#pragma unroll
        for (int in = 0; in < 8; in++) {
            S[in][0] = ex2(S[in][0] - nm0);
            S[in][1] = ex2(S[in][1] - nm0);
            S[in][2] = ex2(S[in][2] - nm1);
            S[in][3] = ex2(S[in][3] - nm1);
            sum0 += S[in][0] + S[in][1];
            sum1 += S[in][2] + S[in][3];
        }
        sum0 += __shfl_xor_sync(0xffffffffu, sum0, 1);
        sum0 += __shfl_xor_sync(0xffffffffu, sum0, 2);
        sum1 += __shfl_xor_sync(0xffffffffu, sum1, 1);
        sum1 += __shfl_xor_sync(0xffffffffu, sum1, 2);
        l0 = l0 * cor0 + sum0;  m0 = nm0;
        l1 = l1 * cor1 + sum1;  m1 = nm1;
#pragma unroll
        for (int in = 0; in < 8; in++) {
            O[in][0] *= cor0; O[in][1] *= cor0;
            O[in][2] *= cor1; O[in][3] *= cor1;
        }

#pragma unroll
        for (int kj = 0; kj < 4; kj++) {
            uint32_t pa[4];
            pa[0] = pack_h2(S[2 * kj][0],     S[2 * kj][1]);
            pa[1] = pack_h2(S[2 * kj][2],     S[2 * kj][3]);
            pa[2] = pack_h2(S[2 * kj + 1][0], S[2 * kj + 1][1]);
            pa[3] = pack_h2(S[2 * kj + 1][2], S[2 * kj + 1][3]);
#pragma unroll
            for (int nv = 0; nv < 4; nv++) {
                uint32_t bv[4];
                ldsm4t(bv, cvta_s(Vs + (st * 64 + kj * 16 + ((lane >> 3) & 1) * 8
                                        + (lane & 7)) * 72 + nv * 16 + (lane >> 4) * 8));
                mma16816(O[nv * 2],     pa, &bv[0]);
                mma16816(O[nv * 2 + 1], pa, &bv[2]);
            }
        }
    }
#undef ISSUEKV

    float inv0 = 1.0f / l0, inv1 = 1.0f / l1;
    int nrow0 = q0 + warp * 16 + r;
    size_t base0 = ((size_t)b * Nn + nrow0) * DIM + h * DHd;
    size_t base1 = ((size_t)b * Nn + nrow0 + 8) * DIM + h * DHd;
#pragma unroll
    for (int nv = 0; nv < 8; nv++) {
        int col = nv * 8 + cq;
        *(__half2*)(Out + base0 + col) = __floats2half2_rn(O[nv][0] * inv0, O[nv][1] * inv0);
        *(__half2*)(Out + base1 + col) = __floats2half2_rn(O[nv][2] * inv1, O[nv][3] * inv1);
    }
}

// ---------------------------------------------------------------------------
extern "C" void kernel_launch(void* const* d_in, const int* in_sizes, int n_in,
                              void* d_out, int out_size)
{
    const float* x   = (const float*)d_in[0];
    const float* Wq  = (const float*)d_in[1];
    const float* Wk  = (const float*)d_in[2];
    const float* Wv  = (const float*)d_in[3];
    const float* Wo  = (const float*)d_in[4];
    const float* bo  = (const float*)d_in[5];
    const float* qsc = (const float*)d_in[6];
    const float* ksc = (const float*)d_in[7];
    float* out = (float*)d_out;

    __half *Xh, *Wqkvh, *Woh, *Qh, *Kh, *Vh, *AOh;
    cudaGetSymbolAddress((void**)&Xh,    g_Xh);
    cudaGetSymbolAddress((void**)&Wqkvh, g_Wqkvh);
    cudaGetSymbolAddress((void**)&Woh,   g_Woh);
    cudaGetSymbolAddress((void**)&Qh,    g_Qh);
    cudaGetSymbolAddress((void**)&Kh,    g_Kh);
    cudaGetSymbolAddress((void**)&Vh,    g_Vh);
    cudaGetSymbolAddress((void**)&AOh,   g_AOh);

    const int smem_g = 2 * GSTG2;                                  // 73728
    const int smem_f = (128 * 72 + 6 * 64 * 72) * sizeof(__half);  // 73728
    cudaFuncSetAttribute(hgemm4<0>, cudaFuncAttributeMaxDynamicSharedMemorySize, smem_g);
    cudaFuncSetAttribute(hgemm4<1>, cudaFuncAttributeMaxDynamicSharedMemorySize, smem_g);
    cudaFuncSetAttribute(flash_h,   cudaFuncAttributeMaxDynamicSharedMemorySize, smem_f);

    convert_all<<<4096, 256>>>(x, Wq, Wk, Wv, Wo, Xh, Wqkvh, Woh);

    // fused QKV projection + QK norm: N = 3072 in 128-wide tiles
    hgemm4<1><<<dim3(3 * DIM / 128, Mrows / 128), 256, smem_g>>>(
        Xh, Wqkvh, nullptr, nullptr, Qh, Kh, Vh, qsc, ksc);

    flash_h<<<dim3(Nn / 128, BHh), 256, smem_f>>>(Qh, Kh, Vh, AOh);

    // output projection
    hgemm4<0><<<dim3(DIM / 128, Mrows / 128), 256, smem_g>>>(
        AOh, Woh, bo, out, nullptr, nullptr, nullptr, nullptr, nullptr);
}

// round 9
// speedup vs baseline: 8.5215x; 1.0901x over previous
#include <cuda_runtime.h>
#include <cuda_fp16.h>
#include <math.h>
#include <stdint.h>

#define Bb   2
#define Nn   2048
#define DIM  1024
#define Hh   16
#define DHd  64
#define Mrows (Bb * Nn)          // 4096
#define BHh  (Bb * Hh)           // 32
#define QMULT 0.18033688011112042f   // 0.125 * log2(e)

// fp16 scratch (device globals)
__device__ __half g_Xh[Mrows * DIM];
__device__ __half g_Wqkvh[3 * DIM * DIM];
__device__ __half g_Woh[DIM * DIM];
__device__ __half g_Qh[BHh * Nn * DHd];
__device__ __half g_Kh[BHh * Nn * DHd];
__device__ __half g_Vh[BHh * Nn * DHd];
__device__ __half g_AOh[Mrows * DIM];

// ---------------------------------------------------------------------------
__device__ __forceinline__ uint32_t cvta_s(const void* p) {
    return (uint32_t)__cvta_generic_to_shared(p);
}
__device__ __forceinline__ void ldsm4(uint32_t* r, uint32_t a) {
    asm volatile("ldmatrix.sync.aligned.m8n8.x4.shared.b16 {%0,%1,%2,%3}, [%4];"
                 : "=r"(r[0]), "=r"(r[1]), "=r"(r[2]), "=r"(r[3]) : "r"(a));
}
__device__ __forceinline__ void ldsm4t(uint32_t* r, uint32_t a) {
    asm volatile("ldmatrix.sync.aligned.m8n8.x4.trans.shared.b16 {%0,%1,%2,%3}, [%4];"
                 : "=r"(r[0]), "=r"(r[1]), "=r"(r[2]), "=r"(r[3]) : "r"(a));
}
__device__ __forceinline__ void mma16816(float* c, const uint32_t* a, const uint32_t* b) {
    asm volatile("mma.sync.aligned.m16n8k16.row.col.f32.f16.f16.f32 "
                 "{%0,%1,%2,%3}, {%4,%5,%6,%7}, {%8,%9}, {%0,%1,%2,%3};"
                 : "+f"(c[0]), "+f"(c[1]), "+f"(c[2]), "+f"(c[3])
                 : "r"(a[0]), "r"(a[1]), "r"(a[2]), "r"(a[3]), "r"(b[0]), "r"(b[1]));
}
__device__ __forceinline__ uint32_t pack_h2(float a, float b) {
    __half2 h = __floats2half2_rn(a, b);
    return *reinterpret_cast<uint32_t*>(&h);
}
__device__ __forceinline__ float ex2(float x) {
    float y;
    asm("ex2.approx.ftz.f32 %0, %1;" : "=f"(y) : "f"(x));
    return y;
}

#define CP16(dst, src) asm volatile("cp.async.cg.shared.global [%0], [%1], 16;" \
                                    :: "r"(dst), "l"(src))
#define CPCOMMIT() asm volatile("cp.async.commit_group;")
#define CPWAIT(N)  asm volatile("cp.async.wait_group %0;" :: "n"(N))

// ---------------------------------------------------------------------------
// merged fp32 -> fp16 conversion (unit = 8 floats)
// ---------------------------------------------------------------------------
__global__ __launch_bounds__(256)
void convert_all(const float* __restrict__ x,  const float* __restrict__ Wq,
                 const float* __restrict__ Wk, const float* __restrict__ Wv,
                 const float* __restrict__ Wo,
                 __half* __restrict__ Xh, __half* __restrict__ Wqkvh,
                 __half* __restrict__ Woh)
{
    int i = blockIdx.x * 256 + threadIdx.x;     // 0 .. 1048575
    const float* src;
    __half* dst;
    int j = i;
    if (j < 524288)      { src = x;  dst = Xh; }
    else {
        j -= 524288;
        if (j < 131072)      { src = Wq; dst = Wqkvh; }
        else { j -= 131072;
            if (j < 131072)  { src = Wk; dst = Wqkvh + 1048576; }
            else { j -= 131072;
                if (j < 131072) { src = Wv; dst = Wqkvh + 2097152; }
                else { j -= 131072; src = Wo; dst = Woh; }
            }
        }
    }
    float4 a = ((const float4*)src)[2 * j];
    float4 b = ((const float4*)src)[2 * j + 1];
    __half2 h[4] = { __floats2half2_rn(a.x, a.y), __floats2half2_rn(a.z, a.w),
                     __floats2half2_rn(b.x, b.y), __floats2half2_rn(b.z, b.w) };
    ((int4*)dst)[j] = *reinterpret_cast<int4*>(h);
}

// ---------------------------------------------------------------------------
// fp16 HMMA GEMM: C[m,e] = sum_k A[m,k]*B[e,k], K=1024.
// CTA 128x128, BK=64 (16 iters), 3-STAGE cp.async (load-ahead = 2 iters).
// 8 warps as 4(M) x 2(N): warp tile 32x64. 2 CTAs/SM.
// smem: 3 stages x 36864 B = 110592 B/CTA (2 CTAs = 221 KB <= 227 KB).
// EPI 0: fp32 out + bias. EPI 1: QKV demux + fused per-head L2 norm.
// ---------------------------------------------------------------------------
#define GSTG2 36864          // stage bytes: (128 A rows + 128 B rows) * 144

template <int EPI>
__global__ __launch_bounds__(256, 2)
void hgemm5(const __half* __restrict__ A, const __half* __restrict__ B,
            const float* __restrict__ bias, float* __restrict__ Cf,
            __half* __restrict__ Qo, __half* __restrict__ Ko, __half* __restrict__ Vo,
            const float* __restrict__ qsc, const float* __restrict__ ksc)
{
    extern __shared__ __align__(16) char gsm[];
    const uint32_t sb = cvta_s(gsm);

    const int tid = threadIdx.x;
    const int warp = tid >> 5, lane = tid & 31;
    const int bm = blockIdx.y * 128, bn = blockIdx.x * 128;
    const int wm = (warp >> 1) * 32, wn = (warp & 1) * 64;

    float c[2][8][4];
#pragma unroll
    for (int i = 0; i < 2; i++)
#pragma unroll
        for (int j = 0; j < 8; j++)
#pragma unroll
            for (int q = 0; q < 4; q++) c[i][j][q] = 0.0f;

#define GISSUE(S, KB)                                                          \
    do {                                                                       \
        uint32_t As = sb + (S) * GSTG2;                                        \
        uint32_t Bs = As + 18432;                                              \
        _Pragma("unroll")                                                      \
        for (int it = 0; it < 4; it++) {                                       \
            int id = it * 256 + tid;                                           \
            int m = id >> 3, c8 = id & 7;                                      \
            CP16(As + m * 144 + c8 * 16,                                       \
                 A + (size_t)(bm + m) * 1024 + (KB) + c8 * 8);                 \
            CP16(Bs + m * 144 + c8 * 16,                                       \
                 B + (size_t)(bn + m) * 1024 + (KB) + c8 * 8);                 \
        }                                                                      \
    } while (0)

    GISSUE(0, 0);  CPCOMMIT();
    GISSUE(1, 64); CPCOMMIT();

    for (int kt = 0; kt < 16; kt++) {
        if (kt < 15) CPWAIT(1); else CPWAIT(0);
        __syncthreads();     // stage kt ready; stage (kt+2)%3 drained by all warps

        if (kt + 2 < 16) { GISSUE((kt + 2) % 3, (kt + 2) * 64); CPCOMMIT(); }

        const uint32_t As = sb + (kt % 3) * GSTG2;
        const uint32_t Bs = As + 18432;

#pragma unroll
        for (int s = 0; s < 2; s++) {            // two k32 halves of BK=64
            uint32_t b[8][4];
#pragma unroll
            for (int in = 0; in < 8; in++)
                ldsm4(b[in], Bs + (wn + in * 8 + (lane & 7)) * 144
                               + s * 64 + (lane >> 3) * 16);
#pragma unroll
            for (int ks = 0; ks < 2; ks++) {
                uint32_t a[2][4];
#pragma unroll
                for (int im = 0; im < 2; im++)
                    ldsm4(a[im], As + (wm + im * 16 + (lane & 15)) * 144
                                   + s * 64 + ks * 32 + (lane >> 4) * 16);
#pragma unroll
                for (int im = 0; im < 2; im++)
#pragma unroll
                    for (int in = 0; in < 8; in++)
                        mma16816(c[im][in], a[im], &b[in][ks * 2]);
            }
        }
    }
#undef GISSUE

    // ---- epilogue ----
    const int r = lane >> 2, cq = (lane & 3) * 2;

    if (EPI == 0) {
        float2 bi[8];
#pragma unroll
        for (int in = 0; in < 8; in++)
            bi[in] = *(const float2*)&bias[bn + wn + in * 8 + cq];
#pragma unroll
        for (int im = 0; im < 2; im++)
#pragma unroll
            for (int hm = 0; hm < 2; hm++) {
                int m = bm + wm + im * 16 + hm * 8 + r;
#pragma unroll
                for (int in = 0; in < 8; in++) {
                    int e = bn + wn + in * 8 + cq;
                    *(float2*)&Cf[(size_t)m * 1024 + e] =
                        make_float2(c[im][in][hm * 2] + bi[in].x,
                                    c[im][in][hm * 2 + 1] + bi[in].y);
                }
            }
    } else {
        const int which = bn >> 10;                  // 0=Q 1=K 2=V
        const int bnl = bn & 1023;
        __half* dst = (which == 0) ? Qo : (which == 1) ? Ko : Vo;
        const int h = (bnl + wn) >> 6;               // warp N-tile = one head
        const float mult = (which == 0) ? QMULT : 1.0f;
        const float* sc = (which == 0) ? qsc : ksc;

        float2 s2[8];
        if (which < 2) {
#pragma unroll
            for (int in = 0; in < 8; in++)
                s2[in] = *(const float2*)&sc[h * 64 + in * 8 + cq];
        } else {
#pragma unroll
            for (int in = 0; in < 8; in++) s2[in] = make_float2(1.0f, 1.0f);
        }

#pragma unroll
        for (int im = 0; im < 2; im++)
#pragma unroll
            for (int hm = 0; hm < 2; hm++) {
                float inv = 1.0f;
                if (which < 2) {
                    float ss = 0.0f;
#pragma unroll
                    for (int in = 0; in < 8; in++)
                        ss += c[im][in][hm * 2] * c[im][in][hm * 2]
                            + c[im][in][hm * 2 + 1] * c[im][in][hm * 2 + 1];
                    ss += __shfl_xor_sync(0xffffffffu, ss, 1);
                    ss += __shfl_xor_sync(0xffffffffu, ss, 2);
                    inv = mult / fmaxf(sqrtf(ss), 1e-12f);
                }
                int m = bm + wm + im * 16 + hm * 8 + r;
                int bbq = m >> 11, n = m & 2047;
                __half* row = dst + (size_t)(((bbq * Hh + h) * Nn) + n) * DHd;
#pragma unroll
                for (int in = 0; in < 8; in++) {
                    int dh = in * 8 + cq;
                    *(__half2*)&row[dh] = __floats2half2_rn(
                        c[im][in][hm * 2] * inv * s2[in].x,
                        c[im][in][hm * 2 + 1] * inv * s2[in].y);
                }
            }
    }
}

// ---------------------------------------------------------------------------
// Flash attention WITHOUT online max: logits are base-2 and bounded
// (|q·k| <= ||q_scale_row|| * ||k_scale_row|| after L2 norm; * 0.125*log2e),
// so ex2(S) never overflows and needs no max subtraction. Row sums accumulate
// per-thread across all tiles; single shuffle reduce at the end.
// CTA: 128 queries of one (b,h); 8 warps * 16 rows; 64-key tiles, 32 tiles.
// ---------------------------------------------------------------------------
__global__ __launch_bounds__(256, 2)
void flash_h(const __half* __restrict__ Q, const __half* __restrict__ K,
             const __half* __restrict__ V, __half* __restrict__ Out)
{
    extern __shared__ __half fsm[];
    __half* Qs = fsm;                        // [128][72]
    __half* Ks = fsm + 128 * 72;             // [3][64][72]
    __half* Vs = Ks + 3 * 64 * 72;           // [3][64][72]

    const int tid = threadIdx.x;
    const int warp = tid >> 5, lane = tid & 31;
    const int bh = blockIdx.y;
    const int q0 = blockIdx.x * 128;
    const int b = bh >> 4, h = bh & 15;
    const int r = lane >> 2, cq = (lane & 3) * 2;

    const __half* Qg = Q + ((size_t)bh * Nn + q0) * DHd;
#pragma unroll
    for (int it = 0; it < 4; it++) {
        int id = it * 256 + tid;
        int m = id >> 3, cc = (id & 7) * 8;
        *(int4*)&Qs[m * 72 + cc] = *(const int4*)(Qg + m * DHd + cc);
    }

    const __half* Kg = K + (size_t)bh * Nn * DHd;
    const __half* Vg = V + (size_t)bh * Nn * DHd;

#define ISSUEKV(S, KT)                                                         \
    do {                                                                       \
        _Pragma("unroll")                                                      \
        for (int i = 0; i < 2; i++) {                                          \
            int id = i * 256 + tid;                                            \
            int m = id >> 3, cc = (id & 7) * 8;                                \
            size_t go = (size_t)((KT) * 64 + m) * DHd + cc;                    \
            CP16(cvta_s(Ks + ((S) * 64 + m) * 72 + cc), Kg + go);              \
            CP16(cvta_s(Vs + ((S) * 64 + m) * 72 + cc), Vg + go);              \
        }                                                                      \
    } while (0)

    ISSUEKV(0, 0); CPCOMMIT();
    ISSUEKV(1, 1); CPCOMMIT();
    __syncthreads();                         // Qs visible

    uint32_t aq[4][4];                       // hoisted Q fragments
#pragma unroll
    for (int kq = 0; kq < 4; kq++)
        ldsm4(aq[kq], cvta_s(Qs + (warp * 16 + (lane & 15)) * 72
                                + kq * 16 + (lane >> 4) * 8));

    float O[8][4];
#pragma unroll
    for (int i = 0; i < 8; i++)
#pragma unroll
        for (int j = 0; j < 4; j++) O[i][j] = 0.0f;
    float l0 = 0.0f, l1 = 0.0f;              // per-thread partial row sums

    for (int kt = 0; kt < 32; kt++) {
        if (kt >= 30) CPWAIT(0); else CPWAIT(1);
        __syncthreads();

        if (kt + 2 < 32) { ISSUEKV((kt + 2) % 3, kt + 2); CPCOMMIT(); }

        const int st = kt % 3;

        float S[8][4];
#pragma unroll
        for (int i = 0; i < 8; i++)
#pragma unroll
            for (int j = 0; j < 4; j++) S[i][j] = 0.0f;

#pragma unroll
        for (int kh = 0; kh < 2; kh++) {
#pragma unroll
            for (int in = 0; in < 8; in++) {
                uint32_t bk[4];
                ldsm4(bk, cvta_s(Ks + (st * 64 + in * 8 + (lane & 7)) * 72
                                    + kh * 32 + (lane >> 3) * 8));
                mma16816(S[in], aq[kh * 2],     &bk[0]);
                mma16816(S[in], aq[kh * 2 + 1], &bk[2]);
            }
        }

        // p = 2^S (bounded, no max needed); accumulate per-thread row sums
#pragma unroll
        for (int in = 0; in < 8; in++) {
            S[in][0] = ex2(S[in][0]);
            S[in][1] = ex2(S[in][1]);
            S[in][2] = ex2(S[in][2]);
            S[in][3] = ex2(S[in][3]);
            l0 += S[in][0] + S[in][1];
            l1 += S[in][2] + S[in][3];
        }

        // O += P @ V
#pragma unroll
        for (int kj = 0; kj < 4; kj++) {
            uint32_t pa[4];
            pa[0] = pack_h2(S[2 * kj][0],     S[2 * kj][1]);
            pa[1] = pack_h2(S[2 * kj][2],     S[2 * kj][3]);
            pa[2] = pack_h2(S[2 * kj + 1][0], S[2 * kj + 1][1]);
            pa[3] = pack_h2(S[2 * kj + 1][2], S[2 * kj + 1][3]);
#pragma unroll
            for (int nv = 0; nv < 4; nv++) {
                uint32_t bv[4];
                ldsm4t(bv, cvta_s(Vs + (st * 64 + kj * 16 + ((lane >> 3) & 1) * 8
                                        + (lane & 7)) * 72 + nv * 16 + (lane >> 4) * 8));
                mma16816(O[nv * 2],     pa, &bv[0]);
                mma16816(O[nv * 2 + 1], pa, &bv[2]);
            }
        }
    }
#undef ISSUEKV

    // final row-sum reduce (4 lanes per row) + normalize + store
    l0 += __shfl_xor_sync(0xffffffffu, l0, 1);
    l0 += __shfl_xor_sync(0xffffffffu, l0, 2);
    l1 += __shfl_xor_sync(0xffffffffu, l1, 1);
    l1 += __shfl_xor_sync(0xffffffffu, l1, 2);
    float inv0 = 1.0f / l0, inv1 = 1.0f / l1;

    int nrow0 = q0 + warp * 16 + r;
    size_t base0 = ((size_t)b * Nn + nrow0) * DIM + h * DHd;
    size_t base1 = ((size_t)b * Nn + nrow0 + 8) * DIM + h * DHd;
#pragma unroll
    for (int nv = 0; nv < 8; nv++) {
        int col = nv * 8 + cq;
        *(__half2*)(Out + base0 + col) = __floats2half2_rn(O[nv][0] * inv0, O[nv][1] * inv0);
        *(__half2*)(Out + base1 + col) = __floats2half2_rn(O[nv][2] * inv1, O[nv][3] * inv1);
    }
}

// ---------------------------------------------------------------------------
extern "C" void kernel_launch(void* const* d_in, const int* in_sizes, int n_in,
                              void* d_out, int out_size)
{
    const float* x   = (const float*)d_in[0];
    const float* Wq  = (const float*)d_in[1];
    const float* Wk  = (const float*)d_in[2];
    const float* Wv  = (const float*)d_in[3];
    const float* Wo  = (const float*)d_in[4];
    const float* bo  = (const float*)d_in[5];
    const float* qsc = (const float*)d_in[6];
    const float* ksc = (const float*)d_in[7];
    float* out = (float*)d_out;

    __half *Xh, *Wqkvh, *Woh, *Qh, *Kh, *Vh, *AOh;
    cudaGetSymbolAddress((void**)&Xh,    g_Xh);
    cudaGetSymbolAddress((void**)&Wqkvh, g_Wqkvh);
    cudaGetSymbolAddress((void**)&Woh,   g_Woh);
    cudaGetSymbolAddress((void**)&Qh,    g_Qh);
    cudaGetSymbolAddress((void**)&Kh,    g_Kh);
    cudaGetSymbolAddress((void**)&Vh,    g_Vh);
    cudaGetSymbolAddress((void**)&AOh,   g_AOh);

    const int smem_g = 3 * GSTG2;                                  // 110592
    const int smem_f = (128 * 72 + 6 * 64 * 72) * sizeof(__half);  // 73728
    cudaFuncSetAttribute(hgemm5<0>, cudaFuncAttributeMaxDynamicSharedMemorySize, smem_g);
    cudaFuncSetAttribute(hgemm5<1>, cudaFuncAttributeMaxDynamicSharedMemorySize, smem_g);
    cudaFuncSetAttribute(flash_h,   cudaFuncAttributeMaxDynamicSharedMemorySize, smem_f);

    convert_all<<<4096, 256>>>(x, Wq, Wk, Wv, Wo, Xh, Wqkvh, Woh);

    // fused QKV projection + QK norm: N = 3072 in 128-wide tiles
    hgemm5<1><<<dim3(3 * DIM / 128, Mrows / 128), 256, smem_g>>>(
        Xh, Wqkvh, nullptr, nullptr, Qh, Kh, Vh, qsc, ksc);

    flash_h<<<dim3(Nn / 128, BHh), 256, smem_f>>>(Qh, Kh, Vh, AOh);

    // output projection
    hgemm5<0><<<dim3(DIM / 128, Mrows / 128), 256, smem_g>>>(
        AOh, Woh, bo, out, nullptr, nullptr, nullptr, nullptr, nullptr);
}